// round 11
// baseline (speedup 1.0000x reference)
#include <cuda_runtime.h>
#include <cuda_fp16.h>
#include <cstdint>

#define L_Q   4096
#define L_CTX 4097
#define C_DIM 320
#define N_HEADS 8
#define DHEAD 40
#define DPAD  48
#define WSZ   (C_DIM * C_DIM)   // 102400

// ---------------- device scratch (no allocations allowed) ----------------
__device__ __half g_ctx_h[(size_t)L_CTX * C_DIM];
__device__ __half g_ctx_l[(size_t)L_CTX * C_DIM];
__device__ __half g_w_h[4 * WSZ];
__device__ __half g_w_l[4 * WSZ];
__device__ __half g_q[(size_t)N_HEADS * L_Q * DPAD];    // d 40..47 zero
__device__ __half g_k[(size_t)N_HEADS * L_CTX * DPAD];
__device__ __half g_v[(size_t)N_HEADS * L_CTX * DPAD];
__device__ __half g_oh[(size_t)L_Q * C_DIM];
__device__ __half g_ol[(size_t)L_Q * C_DIM];
__device__ unsigned g_mbits[(size_t)L_Q * 128];         // fragment-order packed mask bits
__device__ int    g_mask_is_u8;

#define LOG2E 1.4426950408889634f

// ---------------- helpers ----------------
__device__ __forceinline__ void mma16816(float* d, const uint32_t* a, const uint32_t* b) {
    asm volatile(
        "mma.sync.aligned.m16n8k16.row.col.f32.f16.f16.f32 "
        "{%0,%1,%2,%3}, {%4,%5,%6,%7}, {%8,%9}, {%0,%1,%2,%3};"
        : "+f"(d[0]), "+f"(d[1]), "+f"(d[2]), "+f"(d[3])
        : "r"(a[0]), "r"(a[1]), "r"(a[2]), "r"(a[3]), "r"(b[0]), "r"(b[1]));
}
__device__ __forceinline__ void mma16816_f16(uint32_t* d, const uint32_t* a, const uint32_t* b) {
    asm volatile(
        "mma.sync.aligned.m16n8k16.row.col.f16.f16.f16.f16 "
        "{%0,%1}, {%2,%3,%4,%5}, {%6,%7}, {%0,%1};"
        : "+r"(d[0]), "+r"(d[1])
        : "r"(a[0]), "r"(a[1]), "r"(a[2]), "r"(a[3]), "r"(b[0]), "r"(b[1]));
}
__device__ __forceinline__ void mma16808_f16(uint32_t* d, const uint32_t* a, uint32_t b) {
    asm volatile(
        "mma.sync.aligned.m16n8k8.row.col.f16.f16.f16.f16 "
        "{%0,%1}, {%2,%3}, {%4}, {%0,%1};"
        : "+r"(d[0]), "+r"(d[1])
        : "r"(a[0]), "r"(a[1]), "r"(b));
}
__device__ __forceinline__ void ldsm4(uint32_t* r, uint32_t saddr) {
    asm volatile("ldmatrix.sync.aligned.m8n8.x4.shared.b16 {%0,%1,%2,%3}, [%4];"
                 : "=r"(r[0]), "=r"(r[1]), "=r"(r[2]), "=r"(r[3]) : "r"(saddr));
}
__device__ __forceinline__ void ldsm2(uint32_t* r, uint32_t saddr) {
    asm volatile("ldmatrix.sync.aligned.m8n8.x2.shared.b16 {%0,%1}, [%2];"
                 : "=r"(r[0]), "=r"(r[1]) : "r"(saddr));
}
__device__ __forceinline__ void ldsm2t(uint32_t* r, uint32_t saddr) {
    asm volatile("ldmatrix.sync.aligned.m8n8.x2.trans.shared.b16 {%0,%1}, [%2];"
                 : "=r"(r[0]), "=r"(r[1]) : "r"(saddr));
}
__device__ __forceinline__ void split_h(float v, __half& h, __half& l) {
    h = __float2half_rn(v);
    l = __float2half_rn(v - __half2float(h));
}
__device__ __forceinline__ float ex2f(float x) {
    float y; asm("ex2.approx.f32 %0, %1;" : "=f"(y) : "f"(x)); return y;
}
__device__ __forceinline__ uint32_t hexp2_u(uint32_t x) {
    uint32_t y; asm("ex2.approx.f16x2 %0, %1;" : "=r"(y) : "r"(x)); return y;
}
__device__ __forceinline__ __half2 u2h(uint32_t u) { return *(__half2*)&u; }
__device__ __forceinline__ void cp_async16(uint32_t dst, const void* src) {
    asm volatile("cp.async.cg.shared.global [%0], [%1], 16;" :: "r"(dst), "l"(src));
}

// ---------------- kernel 0: detect mask dtype ----------------
__global__ void detect_mask_kernel(const unsigned char* __restrict__ mask) {
    __shared__ int cnt[256];
    int tid = threadIdx.x;
    int c = 0;
    for (int i = tid; i < 4096; i += 256) c += (mask[i] != 0);
    cnt[tid] = c;
    __syncthreads();
    for (int s = 128; s; s >>= 1) {
        if (tid < s) cnt[tid] += cnt[tid + s];
        __syncthreads();
    }
    if (tid == 0) g_mask_is_u8 = (cnt[0] > 1024) ? 1 : 0;
}

// ---------------- kernel 0b: pack mask bits in MMA-fragment order ----------------
__global__ void pack_mask_kernel(const void* __restrict__ mask) {
    int unit = blockIdx.x * 8 + (threadIdx.x >> 5);
    int lane = threadIdx.x & 31;
    int row = unit >> 7;
    int rem = unit & 127;
    int t = rem >> 1, half = rem & 1;
    int qc = half * 2 + (lane >> 4);
    int v = (lane >> 1) & 7, j = lane & 1;
    int col = t * 64 + v * 8 + qc * 2 + j;
    int val = g_mask_is_u8 ? (int)((const unsigned char*)mask)[(size_t)row * 4096 + col]
                           : ((const int*)mask)[(size_t)row * 4096 + col];
    unsigned bal = __ballot_sync(0xffffffffu, val != 0);
    if (lane == 0) g_mbits[(size_t)row * 128 + rem] = bal;
}

// ---------------- kernel 0c: split weights ----------------
__global__ void split_w_kernel(const float* __restrict__ Wq, const float* __restrict__ Wk,
                               const float* __restrict__ Wv, const float* __restrict__ Wo) {
    int which = blockIdx.y;
    const float* W = (which == 0) ? Wq : (which == 1) ? Wk : (which == 2) ? Wv : Wo;
    int idx = blockIdx.x * 256 + threadIdx.x;
    float v = W[idx];
    __half h, l;
    split_h(v, h, l);
    g_w_h[which * WSZ + idx] = h;
    g_w_l[which * WSZ + idx] = l;
}

// ---------------- kernel 1: build context ----------------
__global__ void build_ctx_kernel(const float* __restrict__ feat,
                                 const float* __restrict__ reg) {
    __shared__ float tile[32][33];
    int c0 = blockIdx.x * 32, x0 = blockIdx.y * 32, t = blockIdx.z;
    int lt = threadIdx.y * 32 + threadIdx.x;
    if (blockIdx.x == 0 && blockIdx.y == 0 && t == 0) {
        for (int c = lt; c < C_DIM; c += 256) {
            __half h, l;
            split_h(reg[c], h, l);
            g_ctx_h[c] = h;
            g_ctx_l[c] = l;
        }
    }
#pragma unroll
    for (int j = 0; j < 32; j += 8)
        tile[threadIdx.y + j][threadIdx.x] =
            feat[((size_t)(t * C_DIM + c0 + threadIdx.y + j)) * 256 + x0 + threadIdx.x];
    __syncthreads();
#pragma unroll
    for (int j = 0; j < 32; j += 8) {
        float v = tile[threadIdx.x][threadIdx.y + j];
        __half h, l;
        split_h(v, h, l);
        size_t off = (size_t)(1 + t * 256 + x0 + threadIdx.y + j) * C_DIM + c0 + threadIdx.x;
        g_ctx_h[off] = h;
        g_ctx_l[off] = l;
    }
}

// ---------------- kernel 2: fused QKV projection, fp16 HMMA ----------------
__global__ void __launch_bounds__(256) qkv_hmma_kernel() {
    __shared__ __half sAh[128 * 40], sAl[128 * 40];
    __shared__ __half sBh[32 * 72],  sBl[32 * 72];

    int by = blockIdx.y;
    int z = by / 5;
    int rows = (z == 0) ? L_Q : L_CTX;
    int ashift = (z == 0) ? 1 : 0;
    int row0 = blockIdx.x * 128;
    if (row0 >= rows) return;
    int ncol0 = (by % 5) * 64;

    int tid = threadIdx.x;
    int w = tid >> 5, lane = tid & 31;
    int g = lane >> 2, qc = lane & 3;
    int wrow = w * 16;

    uint32_t sAhb = (uint32_t)__cvta_generic_to_shared(sAh);
    uint32_t sAlb = (uint32_t)__cvta_generic_to_shared(sAl);
    uint32_t sBhb = (uint32_t)__cvta_generic_to_shared(sBh);
    uint32_t sBlb = (uint32_t)__cvta_generic_to_shared(sBl);

    float acc[8][4] = {};

    for (int k0 = 0; k0 < C_DIM; k0 += 32) {
        __syncthreads();
#pragma unroll
        for (int i = 0; i < 2; i++) {
            int id = tid + i * 256;
            int r = id >> 2, c = (id & 3) * 8;
            uint4 vh = make_uint4(0, 0, 0, 0), vl = vh;
            if (row0 + r < rows) {
                size_t off = (size_t)(row0 + r + ashift) * C_DIM + k0 + c;
                vh = *(const uint4*)&g_ctx_h[off];
                vl = *(const uint4*)&g_ctx_l[off];
            }
            *(uint4*)&sAh[r * 40 + c] = vh;
            *(uint4*)&sAl[r * 40 + c] = vl;
        }
        {
            int r = tid >> 3, c = (tid & 7) * 8;
            size_t off = (size_t)z * WSZ + (size_t)(k0 + r) * C_DIM + ncol0 + c;
            *(uint4*)&sBh[r * 72 + c] = *(const uint4*)&g_w_h[off];
            *(uint4*)&sBl[r * 72 + c] = *(const uint4*)&g_w_l[off];
        }
        __syncthreads();

#pragma unroll
        for (int kk = 0; kk < 2; kk++) {
            uint32_t ah[4], al[4];
            uint32_t aoff = (uint32_t)(((wrow + (lane & 15)) * 40 + kk * 16 + ((lane >> 4) << 3)) * 2);
            ldsm4(ah, sAhb + aoff);
            ldsm4(al, sAlb + aoff);
#pragma unroll
            for (int nt = 0; nt < 8; nt++) {
                uint32_t bh[2], bl[2];
                uint32_t boff = (uint32_t)(((kk * 16 + (lane & 15)) * 72 + nt * 8) * 2);
                ldsm2t(bh, sBhb + boff);
                ldsm2t(bl, sBlb + boff);
                mma16816(acc[nt], ah, bh);
                mma16816(acc[nt], ah, bl);
                mma16816(acc[nt], al, bh);
            }
        }
    }

    float scale = (z == 0) ? (rsqrtf((float)DHEAD) * LOG2E) : 1.0f;
    __half* out = (z == 0) ? g_q : ((z == 1) ? g_k : g_v);
    int r0 = row0 + wrow + g;
    int r1 = r0 + 8;
#pragma unroll
    for (int nt = 0; nt < 8; nt++) {
        int col = ncol0 + nt * 8 + qc * 2;
        int hh = col / DHEAD;
        int d = col - hh * DHEAD;
        if (r0 < rows) {
            out[((size_t)hh * rows + r0) * DPAD + d]     = __float2half(acc[nt][0] * scale);
            out[((size_t)hh * rows + r0) * DPAD + d + 1] = __float2half(acc[nt][1] * scale);
        }
        if (r1 < rows) {
            out[((size_t)hh * rows + r1) * DPAD + d]     = __float2half(acc[nt][2] * scale);
            out[((size_t)hh * rows + r1) * DPAD + d + 1] = __float2half(acc[nt][3] * scale);
        }
    }
}

// ---------------- kernel 3: flash attention ----------------
// fixed-shift softmax (m=0), bit-mask post-exp via LUT, l in registers,
// S: 2x k16 + 1x k8 (skips zero pad dims 40..47); PV: 5 n-tiles (N=40).
#define FLASH_SMEM 61440
__global__ void __launch_bounds__(256, 2) flash_kernel() {
    extern __shared__ __half dsm[];
    __half* sQ     = dsm;                    // 128*56 halfs
    __half* sKbase = dsm + 7168;             // 3 stages * 3584 halfs
    __half* sVbase = dsm + 7168 + 3 * 3584;
    uint4*  sLUT   = (uint4*)(dsm + 28672);  // 256 entries * 16B

    int qb = blockIdx.x, h = blockIdx.y;
    int q0 = qb * 128;
    int tid = threadIdx.x;
    int w = tid >> 5, lane = tid & 31;
    int g = lane >> 2, qc = lane & 3;

    const __half* qg = g_q + (size_t)h * L_Q * DPAD;
    const __half* kg = g_k + (size_t)h * L_CTX * DPAD;
    const __half* vg = g_v + (size_t)h * L_CTX * DPAD;

    uint32_t sK0 = (uint32_t)__cvta_generic_to_shared(sKbase);
    uint32_t sV0 = (uint32_t)__cvta_generic_to_shared(sVbase);

    if (tid < 256) {
        uint32_t e0 = ((tid & 1)   ? 0xFFFFu : 0u) | ((tid & 2)   ? 0xFFFF0000u : 0u);
        uint32_t e1 = ((tid & 4)   ? 0xFFFFu : 0u) | ((tid & 8)   ? 0xFFFF0000u : 0u);
        uint32_t e2 = ((tid & 16)  ? 0xFFFFu : 0u) | ((tid & 32)  ? 0xFFFF0000u : 0u);
        uint32_t e3 = ((tid & 64)  ? 0xFFFFu : 0u) | ((tid & 128) ? 0xFFFF0000u : 0u);
        sLUT[tid] = make_uint4(e0, e1, e2, e3);
    }

    // issue K/V stages 0 and 1
#pragma unroll
    for (int st = 0; st < 2; st++) {
        uint32_t ob = (uint32_t)(st * 7168);
#pragma unroll
        for (int i = 0; i < 3; i++) {
            int id = tid + i * 256;
            int cid = (id < 384) ? id : id - 384;
            int r = cid / 6, p = cid - r * 6;
            const __half* src = (id < 384) ? kg : vg;
            uint32_t dstb = ((id < 384) ? sK0 : sV0) + ob;
            cp_async16(dstb + (uint32_t)((r * 56 + p * 8) * 2),
                       src + (size_t)(1 + st * 64 + r) * DPAD + p * 8);
        }
        asm volatile("cp.async.commit_group;");
    }

    // Q tile
    for (int idx = tid; idx < 128 * 6; idx += 256) {
        int r = idx / 6, p = idx - r * 6;
        *(uint4*)&sQ[r * 56 + p * 8] =
            *(const uint4*)&qg[(size_t)(q0 + r) * DPAD + p * 8];
    }
    __syncthreads();

    // Q fragments: 2x k16 + 1x k8 (dims 32..39)
    uint32_t aQ[2][4], aQ8[2];
    uint32_t sQb = (uint32_t)__cvta_generic_to_shared(sQ);
    int wrow = w * 16;
#pragma unroll
    for (int kk = 0; kk < 2; kk++) {
        uint32_t addr = sQb +
            (uint32_t)(((wrow + (lane & 15)) * 56 + kk * 16 + ((lane >> 4) << 3)) * 2);
        ldsm4(aQ[kk], addr);
    }
    {
        uint32_t addr = sQb + (uint32_t)(((wrow + (lane & 15)) * 56 + 32) * 2);
        ldsm2(aQ8, addr);
    }

    int r0 = wrow + g;
    int r1 = r0 + 8;

    // register token: p_reg = exp2(s_reg) (q pre-scaled by scale*log2e)
    float s0 = 0.f, s1 = 0.f;
#pragma unroll
    for (int d = 0; d < DHEAD; d++) {
        float kd = __half2float(kg[d]);
        s0 += __half2float(qg[(size_t)(q0 + r0) * DPAD + d]) * kd;
        s1 += __half2float(qg[(size_t)(q0 + r1) * DPAD + d]) * kd;
    }
    float pr0f = ex2f(s0), pr1f = ex2f(s1);

    // O accum: 5 n-tiles (dims 0..39); l accumulated in registers
    float o[5][4];
#pragma unroll
    for (int v = 0; v < 5; v++) {
        float v0 = __half2float(vg[v * 8 + qc * 2]);
        float v1 = __half2float(vg[v * 8 + qc * 2 + 1]);
        o[v][0] = pr0f * v0; o[v][1] = pr0f * v1;
        o[v][2] = pr1f * v0; o[v][3] = pr1f * v1;
    }
    float lac0 = 0.f, lac1 = 0.f;

    const uint16_t* mrow0 = (const uint16_t*)(g_mbits + (size_t)(q0 + r0) * 128);
    const uint16_t* mrow1 = (const uint16_t*)(g_mbits + (size_t)(q0 + r1) * 128);

    for (int t = 0; t < 64; t++) {
        if (t < 63) asm volatile("cp.async.wait_group 1;");
        else        asm volatile("cp.async.wait_group 0;");
        __syncthreads();

        // prefetch stage t+2
        if (t + 2 < 64) {
            int st = t + 2;
            uint32_t ob = (uint32_t)((st % 3) * 7168);
#pragma unroll
            for (int i = 0; i < 3; i++) {
                int id = tid + i * 256;
                int cid = (id < 384) ? id : id - 384;
                int r = cid / 6, p = cid - r * 6;
                const __half* src = (id < 384) ? kg : vg;
                uint32_t dstb = ((id < 384) ? sK0 : sV0) + ob;
                cp_async16(dstb + (uint32_t)((r * 56 + p * 8) * 2),
                           src + (size_t)(1 + st * 64 + r) * DPAD + p * 8);
            }
            asm volatile("cp.async.commit_group;");
        }

        uint32_t sKb = sK0 + (uint32_t)((t % 3) * 7168);
        uint32_t sVb = sV0 + (uint32_t)((t % 3) * 7168);

        uint32_t b16_0 = mrow0[t * 4 + qc];
        uint32_t b16_1 = mrow1[t * 4 + qc];

        // ---- S = Q K^T (f16 accumulators, zero init): 2x k16 + 1x k8 ----
        uint32_t sd[8][2];
#pragma unroll
        for (int v = 0; v < 8; v++) { sd[v][0] = 0u; sd[v][1] = 0u; }
#pragma unroll
        for (int kk = 0; kk < 2; kk++) {
#pragma unroll
            for (int pr = 0; pr < 4; pr++) {
                uint32_t b[4];
                uint32_t addr = sKb +
                    (uint32_t)(((pr * 16 + (lane & 15)) * 56 + kk * 16 + ((lane >> 4) << 3)) * 2);
                ldsm4(b, addr);
                uint32_t b0[2] = {b[0], b[2]};
                uint32_t b1[2] = {b[1], b[3]};
                mma16816_f16(sd[2 * pr],     aQ[kk], b0);
                mma16816_f16(sd[2 * pr + 1], aQ[kk], b1);
            }
        }
#pragma unroll
        for (int pr = 0; pr < 4; pr++) {
            uint32_t b2[2];
            uint32_t addr = sKb +
                (uint32_t)(((pr * 16 + (lane & 15)) * 56 + 32) * 2);
            ldsm2(b2, addr);
            mma16808_f16(sd[2 * pr],     aQ8, b2[0]);
            mma16808_f16(sd[2 * pr + 1], aQ8, b2[1]);
        }

        uint4 mA0 = sLUT[b16_0 & 255], mB0 = sLUT[b16_0 >> 8];
        uint4 mA1 = sLUT[b16_1 & 255], mB1 = sLUT[b16_1 >> 8];

        // ---- P = exp2(S), then zero masked entries ----
#pragma unroll
        for (int v = 0; v < 8; v++) {
            sd[v][0] = hexp2_u(sd[v][0]);
            sd[v][1] = hexp2_u(sd[v][1]);
        }
        sd[0][0] &= mA0.x; sd[1][0] &= mA0.y; sd[2][0] &= mA0.z; sd[3][0] &= mA0.w;
        sd[4][0] &= mB0.x; sd[5][0] &= mB0.y; sd[6][0] &= mB0.z; sd[7][0] &= mB0.w;
        sd[0][1] &= mA1.x; sd[1][1] &= mA1.y; sd[2][1] &= mA1.z; sd[3][1] &= mA1.w;
        sd[4][1] &= mB1.x; sd[5][1] &= mB1.y; sd[6][1] &= mB1.z; sd[7][1] &= mB1.w;

        // ---- l partial sums: fp16 tree (depth 3, magnitude <= ~24) -> f32 ----
        {
            __half2 t0 = __hadd2(__hadd2(__hadd2(u2h(sd[0][0]), u2h(sd[1][0])),
                                         __hadd2(u2h(sd[2][0]), u2h(sd[3][0]))),
                                 __hadd2(__hadd2(u2h(sd[4][0]), u2h(sd[5][0])),
                                         __hadd2(u2h(sd[6][0]), u2h(sd[7][0]))));
            float2 f0 = __half22float2(t0);
            lac0 += f0.x + f0.y;
            __half2 t1 = __hadd2(__hadd2(__hadd2(u2h(sd[0][1]), u2h(sd[1][1])),
                                         __hadd2(u2h(sd[2][1]), u2h(sd[3][1]))),
                                 __hadd2(__hadd2(u2h(sd[4][1]), u2h(sd[5][1])),
                                         __hadd2(u2h(sd[6][1]), u2h(sd[7][1]))));
            float2 f1 = __half22float2(t1);
            lac1 += f1.x + f1.y;
        }

        // ---- O += P V : 5 n-tiles ----
#pragma unroll
        for (int kk = 0; kk < 4; kk++) {
            uint32_t pa[4] = {sd[2 * kk][0], sd[2 * kk][1],
                              sd[2 * kk + 1][0], sd[2 * kk + 1][1]};
#pragma unroll
            for (int v = 0; v < 5; v++) {
                uint32_t b[2];
                uint32_t addr = sVb +
                    (uint32_t)(((kk * 16 + (lane & 15)) * 56 + v * 8) * 2);
                ldsm2t(b, addr);
                mma16816(o[v], pa, b);
            }
        }
    }

    // ---- epilogue: reduce l across qc lanes, add register token, normalize ----
    lac0 += __shfl_xor_sync(0xffffffffu, lac0, 1);
    lac0 += __shfl_xor_sync(0xffffffffu, lac0, 2);
    lac1 += __shfl_xor_sync(0xffffffffu, lac1, 1);
    lac1 += __shfl_xor_sync(0xffffffffu, lac1, 2);
    float inv0 = 1.f / (lac0 + pr0f);
    float inv1 = 1.f / (lac1 + pr1f);

    __half* ogh = g_oh + (size_t)q0 * C_DIM + h * DHEAD;
    __half* ogl = g_ol + (size_t)q0 * C_DIM + h * DHEAD;
#pragma unroll
    for (int v = 0; v < 5; v++) {
        int n = v * 8 + qc * 2;
        float f00 = o[v][0] * inv0, f01 = o[v][1] * inv0;
        float f10 = o[v][2] * inv1, f11 = o[v][3] * inv1;
        __half h00, l00, h01, l01, h10, l10, h11, l11;
        split_h(f00, h00, l00); split_h(f01, h01, l01);
        split_h(f10, h10, l10); split_h(f11, h11, l11);
        *(__half2*)&ogh[(size_t)r0 * C_DIM + n] = __halves2half2(h00, h01);
        *(__half2*)&ogl[(size_t)r0 * C_DIM + n] = __halves2half2(l00, l01);
        *(__half2*)&ogh[(size_t)r1 * C_DIM + n] = __halves2half2(h10, h11);
        *(__half2*)&ogl[(size_t)r1 * C_DIM + n] = __halves2half2(l10, l11);
    }
}

// ---------------- kernel 4: output projection, fp16 HMMA ----------------
__global__ void __launch_bounds__(256) out_hmma_kernel(const float* __restrict__ bo,
                                                       float* __restrict__ out) {
    __shared__ __half sAh[128 * 40], sAl[128 * 40];
    __shared__ __half sBh[32 * 72],  sBl[32 * 72];

    int row0 = blockIdx.x * 128;
    int ncol0 = blockIdx.y * 64;

    int tid = threadIdx.x;
    int w = tid >> 5, lane = tid & 31;
    int g = lane >> 2, qc = lane & 3;
    int wrow = w * 16;

    uint32_t sAhb = (uint32_t)__cvta_generic_to_shared(sAh);
    uint32_t sAlb = (uint32_t)__cvta_generic_to_shared(sAl);
    uint32_t sBhb = (uint32_t)__cvta_generic_to_shared(sBh);
    uint32_t sBlb = (uint32_t)__cvta_generic_to_shared(sBl);

    float acc[8][4] = {};

    for (int k0 = 0; k0 < C_DIM; k0 += 32) {
        __syncthreads();
#pragma unroll
        for (int i = 0; i < 2; i++) {
            int id = tid + i * 256;
            int r = id >> 2, c = (id & 3) * 8;
            size_t off = (size_t)(row0 + r) * C_DIM + k0 + c;
            *(uint4*)&sAh[r * 40 + c] = *(const uint4*)&g_oh[off];
            *(uint4*)&sAl[r * 40 + c] = *(const uint4*)&g_ol[off];
        }
        {
            int r = tid >> 3, c = (tid & 7) * 8;
            size_t off = (size_t)3 * WSZ + (size_t)(k0 + r) * C_DIM + ncol0 + c;
            *(uint4*)&sBh[r * 72 + c] = *(const uint4*)&g_w_h[off];
            *(uint4*)&sBl[r * 72 + c] = *(const uint4*)&g_w_l[off];
        }
        __syncthreads();

#pragma unroll
        for (int kk = 0; kk < 2; kk++) {
            uint32_t ah[4], al[4];
            uint32_t aoff = (uint32_t)(((wrow + (lane & 15)) * 40 + kk * 16 + ((lane >> 4) << 3)) * 2);
            ldsm4(ah, sAhb + aoff);
            ldsm4(al, sAlb + aoff);
#pragma unroll
            for (int nt = 0; nt < 8; nt++) {
                uint32_t bh[2], bl[2];
                uint32_t boff = (uint32_t)(((kk * 16 + (lane & 15)) * 72 + nt * 8) * 2);
                ldsm2t(bh, sBhb + boff);
                ldsm2t(bl, sBlb + boff);
                mma16816(acc[nt], ah, bh);
                mma16816(acc[nt], ah, bl);
                mma16816(acc[nt], al, bh);
            }
        }
    }

    int r0 = row0 + wrow + g;
    int r1 = r0 + 8;
    int p0 = (r0 & 255) * 16 + (r0 >> 8);
    int p1 = (r1 & 255) * 16 + (r1 >> 8);
#pragma unroll
    for (int nt = 0; nt < 8; nt++) {
        int col = ncol0 + nt * 8 + qc * 2;
        float b0 = bo[col], b1 = bo[col + 1];
        *(float2*)&out[(size_t)p0 * C_DIM + col] =
            make_float2(acc[nt][0] + b0, acc[nt][1] + b1);
        *(float2*)&out[(size_t)p1 * C_DIM + col] =
            make_float2(acc[nt][2] + b0, acc[nt][3] + b1);
    }
}

// ---------------- launch ----------------
extern "C" void kernel_launch(void* const* d_in, const int* in_sizes, int n_in,
                              void* d_out, int out_size) {
    const float* feat         = (const float*)d_in[0];
    const unsigned char* mask = (const unsigned char*)d_in[1];
    const float* Wq           = (const float*)d_in[2];
    const float* Wk           = (const float*)d_in[3];
    const float* Wv           = (const float*)d_in[4];
    const float* reg          = (const float*)d_in[5];
    const float* Wo           = (const float*)d_in[6];
    const float* bo           = (const float*)d_in[7];
    float* out                = (float*)d_out;

    (void)in_sizes; (void)n_in; (void)out_size;

    detect_mask_kernel<<<1, 256>>>(mask);
    pack_mask_kernel<<<65536, 256>>>(mask);
    split_w_kernel<<<dim3(WSZ / 256, 4), 256>>>(Wq, Wk, Wv, Wo);
    build_ctx_kernel<<<dim3(10, 8, 16), dim3(32, 8)>>>(feat, reg);
    qkv_hmma_kernel<<<dim3(33, 15), 256>>>();

    cudaFuncSetAttribute(flash_kernel,
                         cudaFuncAttributeMaxDynamicSharedMemorySize, FLASH_SMEM);
    flash_kernel<<<dim3(32, N_HEADS), 256, FLASH_SMEM>>>();

    out_hmma_kernel<<<dim3(32, 5), 256>>>(bo, out);
}

// round 12
// speedup vs baseline: 1.0184x; 1.0184x over previous
#include <cuda_runtime.h>
#include <cuda_fp16.h>
#include <cstdint>

#define L_Q   4096
#define L_CTX 4097
#define C_DIM 320
#define N_HEADS 8
#define DHEAD 40
#define DPAD  48
#define WSZ   (C_DIM * C_DIM)   // 102400

// ---------------- device scratch (no allocations allowed) ----------------
__device__ __half g_ctx_h[(size_t)L_CTX * C_DIM];
__device__ __half g_ctx_l[(size_t)L_CTX * C_DIM];
__device__ __half g_w_h[4 * WSZ];
__device__ __half g_w_l[4 * WSZ];
__device__ __half g_q[(size_t)N_HEADS * L_Q * DPAD];    // d 40..47 zero
__device__ __half g_k[(size_t)N_HEADS * L_CTX * DPAD];
__device__ __half g_v[(size_t)N_HEADS * L_CTX * DPAD];
__device__ __half g_oh[(size_t)L_Q * C_DIM];
__device__ __half g_ol[(size_t)L_Q * C_DIM];
__device__ unsigned g_mbits[(size_t)L_Q * 128];         // fragment-order packed mask bits
__device__ int    g_mask_is_u8;

#define LOG2E 1.4426950408889634f

// ---------------- helpers ----------------
__device__ __forceinline__ void mma16816(float* d, const uint32_t* a, const uint32_t* b) {
    asm volatile(
        "mma.sync.aligned.m16n8k16.row.col.f32.f16.f16.f32 "
        "{%0,%1,%2,%3}, {%4,%5,%6,%7}, {%8,%9}, {%0,%1,%2,%3};"
        : "+f"(d[0]), "+f"(d[1]), "+f"(d[2]), "+f"(d[3])
        : "r"(a[0]), "r"(a[1]), "r"(a[2]), "r"(a[3]), "r"(b[0]), "r"(b[1]));
}
__device__ __forceinline__ void mma16816_f16(uint32_t* d, const uint32_t* a, const uint32_t* b) {
    asm volatile(
        "mma.sync.aligned.m16n8k16.row.col.f16.f16.f16.f16 "
        "{%0,%1}, {%2,%3,%4,%5}, {%6,%7}, {%0,%1};"
        : "+r"(d[0]), "+r"(d[1])
        : "r"(a[0]), "r"(a[1]), "r"(a[2]), "r"(a[3]), "r"(b[0]), "r"(b[1]));
}
__device__ __forceinline__ void mma16808_f16(uint32_t* d, const uint32_t* a, uint32_t b) {
    asm volatile(
        "mma.sync.aligned.m16n8k8.row.col.f16.f16.f16.f16 "
        "{%0,%1}, {%2,%3}, {%4}, {%0,%1};"
        : "+r"(d[0]), "+r"(d[1])
        : "r"(a[0]), "r"(a[1]), "r"(b));
}
__device__ __forceinline__ void ldsm4(uint32_t* r, uint32_t saddr) {
    asm volatile("ldmatrix.sync.aligned.m8n8.x4.shared.b16 {%0,%1,%2,%3}, [%4];"
                 : "=r"(r[0]), "=r"(r[1]), "=r"(r[2]), "=r"(r[3]) : "r"(saddr));
}
__device__ __forceinline__ void ldsm2(uint32_t* r, uint32_t saddr) {
    asm volatile("ldmatrix.sync.aligned.m8n8.x2.shared.b16 {%0,%1}, [%2];"
                 : "=r"(r[0]), "=r"(r[1]) : "r"(saddr));
}
__device__ __forceinline__ void ldsm2t(uint32_t* r, uint32_t saddr) {
    asm volatile("ldmatrix.sync.aligned.m8n8.x2.trans.shared.b16 {%0,%1}, [%2];"
                 : "=r"(r[0]), "=r"(r[1]) : "r"(saddr));
}
__device__ __forceinline__ void ldsm4t(uint32_t* r, uint32_t saddr) {
    asm volatile("ldmatrix.sync.aligned.m8n8.x4.trans.shared.b16 {%0,%1,%2,%3}, [%4];"
                 : "=r"(r[0]), "=r"(r[1]), "=r"(r[2]), "=r"(r[3]) : "r"(saddr));
}
__device__ __forceinline__ void split_h(float v, __half& h, __half& l) {
    h = __float2half_rn(v);
    l = __float2half_rn(v - __half2float(h));
}
__device__ __forceinline__ float ex2f(float x) {
    float y; asm("ex2.approx.f32 %0, %1;" : "=f"(y) : "f"(x)); return y;
}
__device__ __forceinline__ uint32_t hexp2_u(uint32_t x) {
    uint32_t y; asm("ex2.approx.f16x2 %0, %1;" : "=r"(y) : "r"(x)); return y;
}
__device__ __forceinline__ __half2 u2h(uint32_t u) { return *(__half2*)&u; }
__device__ __forceinline__ void cp_async16(uint32_t dst, const void* src) {
    asm volatile("cp.async.cg.shared.global [%0], [%1], 16;" :: "r"(dst), "l"(src));
}

// ---------------- kernel 0: detect mask dtype ----------------
__global__ void detect_mask_kernel(const unsigned char* __restrict__ mask) {
    __shared__ int cnt[256];
    int tid = threadIdx.x;
    int c = 0;
    for (int i = tid; i < 4096; i += 256) c += (mask[i] != 0);
    cnt[tid] = c;
    __syncthreads();
    for (int s = 128; s; s >>= 1) {
        if (tid < s) cnt[tid] += cnt[tid + s];
        __syncthreads();
    }
    if (tid == 0) g_mask_is_u8 = (cnt[0] > 1024) ? 1 : 0;
}

// ---------------- kernel 0b: pack mask bits in MMA-fragment order ----------------
__global__ void pack_mask_kernel(const void* __restrict__ mask) {
    int unit = blockIdx.x * 8 + (threadIdx.x >> 5);
    int lane = threadIdx.x & 31;
    int row = unit >> 7;
    int rem = unit & 127;
    int t = rem >> 1, half = rem & 1;
    int qc = half * 2 + (lane >> 4);
    int v = (lane >> 1) & 7, j = lane & 1;
    int col = t * 64 + v * 8 + qc * 2 + j;
    int val = g_mask_is_u8 ? (int)((const unsigned char*)mask)[(size_t)row * 4096 + col]
                           : ((const int*)mask)[(size_t)row * 4096 + col];
    unsigned bal = __ballot_sync(0xffffffffu, val != 0);
    if (lane == 0) g_mbits[(size_t)row * 128 + rem] = bal;
}

// ---------------- kernel 0c: split weights ----------------
__global__ void split_w_kernel(const float* __restrict__ Wq, const float* __restrict__ Wk,
                               const float* __restrict__ Wv, const float* __restrict__ Wo) {
    int which = blockIdx.y;
    const float* W = (which == 0) ? Wq : (which == 1) ? Wk : (which == 2) ? Wv : Wo;
    int idx = blockIdx.x * 256 + threadIdx.x;
    float v = W[idx];
    __half h, l;
    split_h(v, h, l);
    g_w_h[which * WSZ + idx] = h;
    g_w_l[which * WSZ + idx] = l;
}

// ---------------- kernel 1: build context ----------------
__global__ void build_ctx_kernel(const float* __restrict__ feat,
                                 const float* __restrict__ reg) {
    __shared__ float tile[32][33];
    int c0 = blockIdx.x * 32, x0 = blockIdx.y * 32, t = blockIdx.z;
    int lt = threadIdx.y * 32 + threadIdx.x;
    if (blockIdx.x == 0 && blockIdx.y == 0 && t == 0) {
        for (int c = lt; c < C_DIM; c += 256) {
            __half h, l;
            split_h(reg[c], h, l);
            g_ctx_h[c] = h;
            g_ctx_l[c] = l;
        }
    }
#pragma unroll
    for (int j = 0; j < 32; j += 8)
        tile[threadIdx.y + j][threadIdx.x] =
            feat[((size_t)(t * C_DIM + c0 + threadIdx.y + j)) * 256 + x0 + threadIdx.x];
    __syncthreads();
#pragma unroll
    for (int j = 0; j < 32; j += 8) {
        float v = tile[threadIdx.x][threadIdx.y + j];
        __half h, l;
        split_h(v, h, l);
        size_t off = (size_t)(1 + t * 256 + x0 + threadIdx.y + j) * C_DIM + c0 + threadIdx.x;
        g_ctx_h[off] = h;
        g_ctx_l[off] = l;
    }
}

// ---------------- kernel 2: fused QKV projection, fp16 HMMA ----------------
__global__ void __launch_bounds__(256) qkv_hmma_kernel() {
    __shared__ __half sAh[128 * 40], sAl[128 * 40];
    __shared__ __half sBh[32 * 72],  sBl[32 * 72];

    int by = blockIdx.y;
    int z = by / 5;
    int rows = (z == 0) ? L_Q : L_CTX;
    int ashift = (z == 0) ? 1 : 0;
    int row0 = blockIdx.x * 128;
    if (row0 >= rows) return;
    int ncol0 = (by % 5) * 64;

    int tid = threadIdx.x;
    int w = tid >> 5, lane = tid & 31;
    int g = lane >> 2, qc = lane & 3;
    int wrow = w * 16;

    uint32_t sAhb = (uint32_t)__cvta_generic_to_shared(sAh);
    uint32_t sAlb = (uint32_t)__cvta_generic_to_shared(sAl);
    uint32_t sBhb = (uint32_t)__cvta_generic_to_shared(sBh);
    uint32_t sBlb = (uint32_t)__cvta_generic_to_shared(sBl);

    float acc[8][4] = {};

    for (int k0 = 0; k0 < C_DIM; k0 += 32) {
        __syncthreads();
#pragma unroll
        for (int i = 0; i < 2; i++) {
            int id = tid + i * 256;
            int r = id >> 2, c = (id & 3) * 8;
            uint4 vh = make_uint4(0, 0, 0, 0), vl = vh;
            if (row0 + r < rows) {
                size_t off = (size_t)(row0 + r + ashift) * C_DIM + k0 + c;
                vh = *(const uint4*)&g_ctx_h[off];
                vl = *(const uint4*)&g_ctx_l[off];
            }
            *(uint4*)&sAh[r * 40 + c] = vh;
            *(uint4*)&sAl[r * 40 + c] = vl;
        }
        {
            int r = tid >> 3, c = (tid & 7) * 8;
            size_t off = (size_t)z * WSZ + (size_t)(k0 + r) * C_DIM + ncol0 + c;
            *(uint4*)&sBh[r * 72 + c] = *(const uint4*)&g_w_h[off];
            *(uint4*)&sBl[r * 72 + c] = *(const uint4*)&g_w_l[off];
        }
        __syncthreads();

#pragma unroll
        for (int kk = 0; kk < 2; kk++) {
            uint32_t ah[4], al[4];
            uint32_t aoff = (uint32_t)(((wrow + (lane & 15)) * 40 + kk * 16 + ((lane >> 4) << 3)) * 2);
            ldsm4(ah, sAhb + aoff);
            ldsm4(al, sAlb + aoff);
#pragma unroll
            for (int nt = 0; nt < 8; nt++) {
                uint32_t bh[2], bl[2];
                uint32_t boff = (uint32_t)(((kk * 16 + (lane & 15)) * 72 + nt * 8) * 2);
                ldsm2t(bh, sBhb + boff);
                ldsm2t(bl, sBlb + boff);
                mma16816(acc[nt], ah, bh);
                mma16816(acc[nt], ah, bl);
                mma16816(acc[nt], al, bh);
            }
        }
    }

    float scale = (z == 0) ? (rsqrtf((float)DHEAD) * LOG2E) : 1.0f;
    __half* out = (z == 0) ? g_q : ((z == 1) ? g_k : g_v);
    int r0 = row0 + wrow + g;
    int r1 = r0 + 8;
#pragma unroll
    for (int nt = 0; nt < 8; nt++) {
        int col = ncol0 + nt * 8 + qc * 2;
        int hh = col / DHEAD;
        int d = col - hh * DHEAD;
        if (r0 < rows) {
            out[((size_t)hh * rows + r0) * DPAD + d]     = __float2half(acc[nt][0] * scale);
            out[((size_t)hh * rows + r0) * DPAD + d + 1] = __float2half(acc[nt][1] * scale);
        }
        if (r1 < rows) {
            out[((size_t)hh * rows + r1) * DPAD + d]     = __float2half(acc[nt][2] * scale);
            out[((size_t)hh * rows + r1) * DPAD + d + 1] = __float2half(acc[nt][3] * scale);
        }
    }
}

// ---------------- kernel 3: flash attention ----------------
// fixed-shift softmax (m=0), bit-mask post-exp, l in registers,
// S: 2x k16 + 1x k8 f16-accum; PV: f16-accum per tile, promoted to f32 per tile.
#define FLASH_SMEM 61440
__global__ void __launch_bounds__(256, 2) flash_kernel() {
    extern __shared__ __half dsm[];
    __half* sQ     = dsm;                    // 128*56 halfs
    __half* sKbase = dsm + 7168;             // 3 stages * 3584 halfs
    __half* sVbase = dsm + 7168 + 3 * 3584;
    uint4*  sLUT   = (uint4*)(dsm + 28672);  // 256 entries * 16B

    int qb = blockIdx.x, h = blockIdx.y;
    int q0 = qb * 128;
    int tid = threadIdx.x;
    int w = tid >> 5, lane = tid & 31;
    int g = lane >> 2, qc = lane & 3;

    const __half* qg = g_q + (size_t)h * L_Q * DPAD;
    const __half* kg = g_k + (size_t)h * L_CTX * DPAD;
    const __half* vg = g_v + (size_t)h * L_CTX * DPAD;

    uint32_t sK0 = (uint32_t)__cvta_generic_to_shared(sKbase);
    uint32_t sV0 = (uint32_t)__cvta_generic_to_shared(sVbase);

    if (tid < 256) {
        uint32_t e0 = ((tid & 1)   ? 0xFFFFu : 0u) | ((tid & 2)   ? 0xFFFF0000u : 0u);
        uint32_t e1 = ((tid & 4)   ? 0xFFFFu : 0u) | ((tid & 8)   ? 0xFFFF0000u : 0u);
        uint32_t e2 = ((tid & 16)  ? 0xFFFFu : 0u) | ((tid & 32)  ? 0xFFFF0000u : 0u);
        uint32_t e3 = ((tid & 64)  ? 0xFFFFu : 0u) | ((tid & 128) ? 0xFFFF0000u : 0u);
        sLUT[tid] = make_uint4(e0, e1, e2, e3);
    }

    // issue K/V stages 0 and 1
#pragma unroll
    for (int st = 0; st < 2; st++) {
        uint32_t ob = (uint32_t)(st * 7168);
#pragma unroll
        for (int i = 0; i < 3; i++) {
            int id = tid + i * 256;
            int cid = (id < 384) ? id : id - 384;
            int r = cid / 6, p = cid - r * 6;
            const __half* src = (id < 384) ? kg : vg;
            uint32_t dstb = ((id < 384) ? sK0 : sV0) + ob;
            cp_async16(dstb + (uint32_t)((r * 56 + p * 8) * 2),
                       src + (size_t)(1 + st * 64 + r) * DPAD + p * 8);
        }
        asm volatile("cp.async.commit_group;");
    }

    // Q tile
    for (int idx = tid; idx < 128 * 6; idx += 256) {
        int r = idx / 6, p = idx - r * 6;
        *(uint4*)&sQ[r * 56 + p * 8] =
            *(const uint4*)&qg[(size_t)(q0 + r) * DPAD + p * 8];
    }
    __syncthreads();

    // Q fragments: 2x k16 + 1x k8 (dims 32..39)
    uint32_t aQ[2][4], aQ8[2];
    uint32_t sQb = (uint32_t)__cvta_generic_to_shared(sQ);
    int wrow = w * 16;
#pragma unroll
    for (int kk = 0; kk < 2; kk++) {
        uint32_t addr = sQb +
            (uint32_t)(((wrow + (lane & 15)) * 56 + kk * 16 + ((lane >> 4) << 3)) * 2);
        ldsm4(aQ[kk], addr);
    }
    {
        uint32_t addr = sQb + (uint32_t)(((wrow + (lane & 15)) * 56 + 32) * 2);
        ldsm2(aQ8, addr);
    }

    int r0 = wrow + g;
    int r1 = r0 + 8;

    // register token: p_reg = exp2(s_reg) (q pre-scaled by scale*log2e)
    float s0 = 0.f, s1 = 0.f;
#pragma unroll
    for (int d = 0; d < DHEAD; d++) {
        float kd = __half2float(kg[d]);
        s0 += __half2float(qg[(size_t)(q0 + r0) * DPAD + d]) * kd;
        s1 += __half2float(qg[(size_t)(q0 + r1) * DPAD + d]) * kd;
    }
    float pr0f = ex2f(s0), pr1f = ex2f(s1);

    // O accum: 5 n-tiles (dims 0..39) f32 master; l in registers
    float o[5][4];
#pragma unroll
    for (int v = 0; v < 5; v++) {
        float v0 = __half2float(vg[v * 8 + qc * 2]);
        float v1 = __half2float(vg[v * 8 + qc * 2 + 1]);
        o[v][0] = pr0f * v0; o[v][1] = pr0f * v1;
        o[v][2] = pr1f * v0; o[v][3] = pr1f * v1;
    }
    float lac0 = 0.f, lac1 = 0.f;

    const uint16_t* mrow0 = (const uint16_t*)(g_mbits + (size_t)(q0 + r0) * 128);
    const uint16_t* mrow1 = (const uint16_t*)(g_mbits + (size_t)(q0 + r1) * 128);

    for (int t = 0; t < 64; t++) {
        if (t < 63) asm volatile("cp.async.wait_group 1;");
        else        asm volatile("cp.async.wait_group 0;");
        __syncthreads();

        // prefetch stage t+2
        if (t + 2 < 64) {
            int st = t + 2;
            uint32_t ob = (uint32_t)((st % 3) * 7168);
#pragma unroll
            for (int i = 0; i < 3; i++) {
                int id = tid + i * 256;
                int cid = (id < 384) ? id : id - 384;
                int r = cid / 6, p = cid - r * 6;
                const __half* src = (id < 384) ? kg : vg;
                uint32_t dstb = ((id < 384) ? sK0 : sV0) + ob;
                cp_async16(dstb + (uint32_t)((r * 56 + p * 8) * 2),
                           src + (size_t)(1 + st * 64 + r) * DPAD + p * 8);
            }
            asm volatile("cp.async.commit_group;");
        }

        uint32_t sKb = sK0 + (uint32_t)((t % 3) * 7168);
        uint32_t sVb = sV0 + (uint32_t)((t % 3) * 7168);

        uint32_t b16_0 = mrow0[t * 4 + qc];
        uint32_t b16_1 = mrow1[t * 4 + qc];

        // ---- S = Q K^T (f16 accumulators, zero init): 2x k16 + 1x k8 ----
        uint32_t sd[8][2];
#pragma unroll
        for (int v = 0; v < 8; v++) { sd[v][0] = 0u; sd[v][1] = 0u; }
#pragma unroll
        for (int kk = 0; kk < 2; kk++) {
#pragma unroll
            for (int pr = 0; pr < 4; pr++) {
                uint32_t b[4];
                uint32_t addr = sKb +
                    (uint32_t)(((pr * 16 + (lane & 15)) * 56 + kk * 16 + ((lane >> 4) << 3)) * 2);
                ldsm4(b, addr);
                uint32_t b0[2] = {b[0], b[2]};
                uint32_t b1[2] = {b[1], b[3]};
                mma16816_f16(sd[2 * pr],     aQ[kk], b0);
                mma16816_f16(sd[2 * pr + 1], aQ[kk], b1);
            }
        }
#pragma unroll
        for (int pr = 0; pr < 4; pr++) {
            uint32_t b2[2];
            uint32_t addr = sKb +
                (uint32_t)(((pr * 16 + (lane & 15)) * 56 + 32) * 2);
            ldsm2(b2, addr);
            mma16808_f16(sd[2 * pr],     aQ8, b2[0]);
            mma16808_f16(sd[2 * pr + 1], aQ8, b2[1]);
        }

        uint4 mA0 = sLUT[b16_0 & 255], mB0 = sLUT[b16_0 >> 8];
        uint4 mA1 = sLUT[b16_1 & 255], mB1 = sLUT[b16_1 >> 8];

        // ---- P = exp2(S), then zero masked entries ----
#pragma unroll
        for (int v = 0; v < 8; v++) {
            sd[v][0] = hexp2_u(sd[v][0]);
            sd[v][1] = hexp2_u(sd[v][1]);
        }
        sd[0][0] &= mA0.x; sd[1][0] &= mA0.y; sd[2][0] &= mA0.z; sd[3][0] &= mA0.w;
        sd[4][0] &= mB0.x; sd[5][0] &= mB0.y; sd[6][0] &= mB0.z; sd[7][0] &= mB0.w;
        sd[0][1] &= mA1.x; sd[1][1] &= mA1.y; sd[2][1] &= mA1.z; sd[3][1] &= mA1.w;
        sd[4][1] &= mB1.x; sd[5][1] &= mB1.y; sd[6][1] &= mB1.z; sd[7][1] &= mB1.w;

        // ---- l partial sums: fp16 tree -> f32 ----
        {
            __half2 t0 = __hadd2(__hadd2(__hadd2(u2h(sd[0][0]), u2h(sd[1][0])),
                                         __hadd2(u2h(sd[2][0]), u2h(sd[3][0]))),
                                 __hadd2(__hadd2(u2h(sd[4][0]), u2h(sd[5][0])),
                                         __hadd2(u2h(sd[6][0]), u2h(sd[7][0]))));
            float2 f0 = __half22float2(t0);
            lac0 += f0.x + f0.y;
            __half2 t1 = __hadd2(__hadd2(__hadd2(u2h(sd[0][1]), u2h(sd[1][1])),
                                         __hadd2(u2h(sd[2][1]), u2h(sd[3][1]))),
                                 __hadd2(__hadd2(u2h(sd[4][1]), u2h(sd[5][1])),
                                         __hadd2(u2h(sd[6][1]), u2h(sd[7][1]))));
            float2 f1 = __half22float2(t1);
            lac1 += f1.x + f1.y;
        }

        // ---- O_tile = P V in f16 accum (5 n-tiles), promoted to f32 once ----
        uint32_t od[5][2];
#pragma unroll
        for (int v = 0; v < 5; v++) { od[v][0] = 0u; od[v][1] = 0u; }
#pragma unroll
        for (int kk = 0; kk < 4; kk++) {
            uint32_t pa[4] = {sd[2 * kk][0], sd[2 * kk][1],
                              sd[2 * kk + 1][0], sd[2 * kk + 1][1]};
            // v-tiles 0,1 via one ldsm4t
            {
                uint32_t b[4];
                uint32_t addr = sVb +
                    (uint32_t)(((kk * 16 + (lane & 15)) * 56 + ((lane >> 4) << 3)) * 2);
                ldsm4t(b, addr);
                uint32_t t0[2] = {b[0], b[1]};
                uint32_t t1[2] = {b[2], b[3]};
                mma16816_f16(od[0], pa, t0);
                mma16816_f16(od[1], pa, t1);
            }
            // v-tiles 2,3 via one ldsm4t
            {
                uint32_t b[4];
                uint32_t addr = sVb +
                    (uint32_t)(((kk * 16 + (lane & 15)) * 56 + 16 + ((lane >> 4) << 3)) * 2);
                ldsm4t(b, addr);
                uint32_t t2[2] = {b[0], b[1]};
                uint32_t t3[2] = {b[2], b[3]};
                mma16816_f16(od[2], pa, t2);
                mma16816_f16(od[3], pa, t3);
            }
            // v-tile 4 via ldsm2t
            {
                uint32_t b[2];
                uint32_t addr = sVb +
                    (uint32_t)(((kk * 16 + (lane & 15)) * 56 + 32) * 2);
                ldsm2t(b, addr);
                mma16816_f16(od[4], pa, b);
            }
        }
        // promote tile sums to f32 masters
#pragma unroll
        for (int v = 0; v < 5; v++) {
            float2 f0 = __half22float2(u2h(od[v][0]));
            float2 f1 = __half22float2(u2h(od[v][1]));
            o[v][0] += f0.x; o[v][1] += f0.y;
            o[v][2] += f1.x; o[v][3] += f1.y;
        }
    }

    // ---- epilogue: reduce l across qc lanes, add register token, normalize ----
    lac0 += __shfl_xor_sync(0xffffffffu, lac0, 1);
    lac0 += __shfl_xor_sync(0xffffffffu, lac0, 2);
    lac1 += __shfl_xor_sync(0xffffffffu, lac1, 1);
    lac1 += __shfl_xor_sync(0xffffffffu, lac1, 2);
    float inv0 = 1.f / (lac0 + pr0f);
    float inv1 = 1.f / (lac1 + pr1f);

    __half* ogh = g_oh + (size_t)q0 * C_DIM + h * DHEAD;
    __half* ogl = g_ol + (size_t)q0 * C_DIM + h * DHEAD;
#pragma unroll
    for (int v = 0; v < 5; v++) {
        int n = v * 8 + qc * 2;
        float f00 = o[v][0] * inv0, f01 = o[v][1] * inv0;
        float f10 = o[v][2] * inv1, f11 = o[v][3] * inv1;
        __half h00, l00, h01, l01, h10, l10, h11, l11;
        split_h(f00, h00, l00); split_h(f01, h01, l01);
        split_h(f10, h10, l10); split_h(f11, h11, l11);
        *(__half2*)&ogh[(size_t)r0 * C_DIM + n] = __halves2half2(h00, h01);
        *(__half2*)&ogl[(size_t)r0 * C_DIM + n] = __halves2half2(l00, l01);
        *(__half2*)&ogh[(size_t)r1 * C_DIM + n] = __halves2half2(h10, h11);
        *(__half2*)&ogl[(size_t)r1 * C_DIM + n] = __halves2half2(l10, l11);
    }
}

// ---------------- kernel 4: output projection, fp16 HMMA ----------------
__global__ void __launch_bounds__(256) out_hmma_kernel(const float* __restrict__ bo,
                                                       float* __restrict__ out) {
    __shared__ __half sAh[128 * 40], sAl[128 * 40];
    __shared__ __half sBh[32 * 72],  sBl[32 * 72];

    int row0 = blockIdx.x * 128;
    int ncol0 = blockIdx.y * 64;

    int tid = threadIdx.x;
    int w = tid >> 5, lane = tid & 31;
    int g = lane >> 2, qc = lane & 3;
    int wrow = w * 16;

    uint32_t sAhb = (uint32_t)__cvta_generic_to_shared(sAh);
    uint32_t sAlb = (uint32_t)__cvta_generic_to_shared(sAl);
    uint32_t sBhb = (uint32_t)__cvta_generic_to_shared(sBh);
    uint32_t sBlb = (uint32_t)__cvta_generic_to_shared(sBl);

    float acc[8][4] = {};

    for (int k0 = 0; k0 < C_DIM; k0 += 32) {
        __syncthreads();
#pragma unroll
        for (int i = 0; i < 2; i++) {
            int id = tid + i * 256;
            int r = id >> 2, c = (id & 3) * 8;
            size_t off = (size_t)(row0 + r) * C_DIM + k0 + c;
            *(uint4*)&sAh[r * 40 + c] = *(const uint4*)&g_oh[off];
            *(uint4*)&sAl[r * 40 + c] = *(const uint4*)&g_ol[off];
        }
        {
            int r = tid >> 3, c = (tid & 7) * 8;
            size_t off = (size_t)3 * WSZ + (size_t)(k0 + r) * C_DIM + ncol0 + c;
            *(uint4*)&sBh[r * 72 + c] = *(const uint4*)&g_w_h[off];
            *(uint4*)&sBl[r * 72 + c] = *(const uint4*)&g_w_l[off];
        }
        __syncthreads();

#pragma unroll
        for (int kk = 0; kk < 2; kk++) {
            uint32_t ah[4], al[4];
            uint32_t aoff = (uint32_t)(((wrow + (lane & 15)) * 40 + kk * 16 + ((lane >> 4) << 3)) * 2);
            ldsm4(ah, sAhb + aoff);
            ldsm4(al, sAlb + aoff);
#pragma unroll
            for (int nt = 0; nt < 8; nt++) {
                uint32_t bh[2], bl[2];
                uint32_t boff = (uint32_t)(((kk * 16 + (lane & 15)) * 72 + nt * 8) * 2);
                ldsm2t(bh, sBhb + boff);
                ldsm2t(bl, sBlb + boff);
                mma16816(acc[nt], ah, bh);
                mma16816(acc[nt], ah, bl);
                mma16816(acc[nt], al, bh);
            }
        }
    }

    int r0 = row0 + wrow + g;
    int r1 = r0 + 8;
    int p0 = (r0 & 255) * 16 + (r0 >> 8);
    int p1 = (r1 & 255) * 16 + (r1 >> 8);
#pragma unroll
    for (int nt = 0; nt < 8; nt++) {
        int col = ncol0 + nt * 8 + qc * 2;
        float b0 = bo[col], b1 = bo[col + 1];
        *(float2*)&out[(size_t)p0 * C_DIM + col] =
            make_float2(acc[nt][0] + b0, acc[nt][1] + b1);
        *(float2*)&out[(size_t)p1 * C_DIM + col] =
            make_float2(acc[nt][2] + b0, acc[nt][3] + b1);
    }
}

// ---------------- launch ----------------
extern "C" void kernel_launch(void* const* d_in, const int* in_sizes, int n_in,
                              void* d_out, int out_size) {
    const float* feat         = (const float*)d_in[0];
    const unsigned char* mask = (const unsigned char*)d_in[1];
    const float* Wq           = (const float*)d_in[2];
    const float* Wk           = (const float*)d_in[3];
    const float* Wv           = (const float*)d_in[4];
    const float* reg          = (const float*)d_in[5];
    const float* Wo           = (const float*)d_in[6];
    const float* bo           = (const float*)d_in[7];
    float* out                = (float*)d_out;

    (void)in_sizes; (void)n_in; (void)out_size;

    detect_mask_kernel<<<1, 256>>>(mask);
    pack_mask_kernel<<<65536, 256>>>(mask);
    split_w_kernel<<<dim3(WSZ / 256, 4), 256>>>(Wq, Wk, Wv, Wo);
    build_ctx_kernel<<<dim3(10, 8, 16), dim3(32, 8)>>>(feat, reg);
    qkv_hmma_kernel<<<dim3(33, 15), 256>>>();

    cudaFuncSetAttribute(flash_kernel,
                         cudaFuncAttributeMaxDynamicSharedMemorySize, FLASH_SMEM);
    flash_kernel<<<dim3(32, N_HEADS), 256, FLASH_SMEM>>>();

    out_hmma_kernel<<<dim3(32, 5), 256>>>(bo, out);
}

// round 13
// speedup vs baseline: 1.0215x; 1.0031x over previous
#include <cuda_runtime.h>
#include <cuda_fp16.h>
#include <cstdint>

#define L_Q   4096
#define L_CTX 4097
#define C_DIM 320
#define N_HEADS 8
#define DHEAD 40
#define DPAD  48
#define WSZ   (C_DIM * C_DIM)   // 102400

// ---------------- device scratch (no allocations allowed) ----------------
__device__ __half g_ctx_h[(size_t)L_CTX * C_DIM];
__device__ __half g_ctx_l[(size_t)L_CTX * C_DIM];
__device__ __half g_w_h[4 * WSZ];
__device__ __half g_w_l[4 * WSZ];
__device__ __half g_q[(size_t)N_HEADS * L_Q * DPAD];    // d 40..47 zero
__device__ __half g_k[(size_t)N_HEADS * L_CTX * DPAD];
__device__ __half g_v[(size_t)N_HEADS * L_CTX * DPAD];
__device__ __half g_oh[(size_t)L_Q * C_DIM];
__device__ __half g_ol[(size_t)L_Q * C_DIM];
__device__ unsigned g_mbits[(size_t)L_Q * 128];         // fragment-order packed mask bits

#define LOG2E 1.4426950408889634f

// ---------------- helpers ----------------
__device__ __forceinline__ void mma16816(float* d, const uint32_t* a, const uint32_t* b) {
    asm volatile(
        "mma.sync.aligned.m16n8k16.row.col.f32.f16.f16.f32 "
        "{%0,%1,%2,%3}, {%4,%5,%6,%7}, {%8,%9}, {%0,%1,%2,%3};"
        : "+f"(d[0]), "+f"(d[1]), "+f"(d[2]), "+f"(d[3])
        : "r"(a[0]), "r"(a[1]), "r"(a[2]), "r"(a[3]), "r"(b[0]), "r"(b[1]));
}
__device__ __forceinline__ void mma16816_f16(uint32_t* d, const uint32_t* a, const uint32_t* b) {
    asm volatile(
        "mma.sync.aligned.m16n8k16.row.col.f16.f16.f16.f16 "
        "{%0,%1}, {%2,%3,%4,%5}, {%6,%7}, {%0,%1};"
        : "+r"(d[0]), "+r"(d[1])
        : "r"(a[0]), "r"(a[1]), "r"(a[2]), "r"(a[3]), "r"(b[0]), "r"(b[1]));
}
__device__ __forceinline__ void mma16808_f16(uint32_t* d, const uint32_t* a, uint32_t b) {
    asm volatile(
        "mma.sync.aligned.m16n8k8.row.col.f16.f16.f16.f16 "
        "{%0,%1}, {%2,%3}, {%4}, {%0,%1};"
        : "+r"(d[0]), "+r"(d[1])
        : "r"(a[0]), "r"(a[1]), "r"(b));
}
__device__ __forceinline__ void ldsm4(uint32_t* r, uint32_t saddr) {
    asm volatile("ldmatrix.sync.aligned.m8n8.x4.shared.b16 {%0,%1,%2,%3}, [%4];"
                 : "=r"(r[0]), "=r"(r[1]), "=r"(r[2]), "=r"(r[3]) : "r"(saddr));
}
__device__ __forceinline__ void ldsm2(uint32_t* r, uint32_t saddr) {
    asm volatile("ldmatrix.sync.aligned.m8n8.x2.shared.b16 {%0,%1}, [%2];"
                 : "=r"(r[0]), "=r"(r[1]) : "r"(saddr));
}
__device__ __forceinline__ void ldsm2t(uint32_t* r, uint32_t saddr) {
    asm volatile("ldmatrix.sync.aligned.m8n8.x2.trans.shared.b16 {%0,%1}, [%2];"
                 : "=r"(r[0]), "=r"(r[1]) : "r"(saddr));
}
__device__ __forceinline__ void ldsm4t(uint32_t* r, uint32_t saddr) {
    asm volatile("ldmatrix.sync.aligned.m8n8.x4.trans.shared.b16 {%0,%1,%2,%3}, [%4];"
                 : "=r"(r[0]), "=r"(r[1]), "=r"(r[2]), "=r"(r[3]) : "r"(saddr));
}
__device__ __forceinline__ void split_h(float v, __half& h, __half& l) {
    h = __float2half_rn(v);
    l = __float2half_rn(v - __half2float(h));
}
__device__ __forceinline__ float ex2f(float x) {
    float y; asm("ex2.approx.f32 %0, %1;" : "=f"(y) : "f"(x)); return y;
}
__device__ __forceinline__ uint32_t hexp2_u(uint32_t x) {
    uint32_t y; asm("ex2.approx.f16x2 %0, %1;" : "=r"(y) : "r"(x)); return y;
}
__device__ __forceinline__ __half2 u2h(uint32_t u) { return *(__half2*)&u; }
__device__ __forceinline__ void cp_async16(uint32_t dst, const void* src) {
    asm volatile("cp.async.cg.shared.global [%0], [%1], 16;" :: "r"(dst), "l"(src));
}

// ---------------- kernel 1: pack mask bits (self-detecting dtype) ----------------
__global__ void pack_mask_kernel(const void* __restrict__ mask) {
    int unit = blockIdx.x * 8 + (threadIdx.x >> 5);
    int lane = threadIdx.x & 31;
    int row = unit >> 7;
    int rem = unit & 127;
    int t = rem >> 1, half = rem & 1;
    int qc = half * 2 + (lane >> 4);
    int v = (lane >> 1) & 7, j = lane & 1;
    int col = t * 64 + v * 8 + qc * 2 + j;
    // dtype probe: int32 {0,1} words never exceed 1; u8 packing makes words like
    // 0x01010100 > 1. All-32-words-in-{0,1} under u8 has probability ~1e-29.
    unsigned probe = ((const unsigned*)mask)[lane];
    bool is_u8 = __any_sync(0xffffffffu, probe > 1u);
    int val = is_u8 ? (int)((const unsigned char*)mask)[(size_t)row * 4096 + col]
                    : ((const int*)mask)[(size_t)row * 4096 + col];
    unsigned bal = __ballot_sync(0xffffffffu, val != 0);
    if (lane == 0) g_mbits[(size_t)row * 128 + rem] = bal;
}

// ---------------- kernel 2: prep = build context + split weights ----------------
// grid (10, 8, 17): z<16 -> ctx transpose+split for frame z; z==16 -> weight split.
__global__ void prep_kernel(const float* __restrict__ feat, const float* __restrict__ reg,
                            const float* __restrict__ Wq, const float* __restrict__ Wk,
                            const float* __restrict__ Wv, const float* __restrict__ Wo) {
    __shared__ float tile[32][33];
    int z = blockIdx.z;
    int lt = threadIdx.y * 32 + threadIdx.x;
    if (z == 16) {
        int blk = blockIdx.y * 10 + blockIdx.x;   // 0..79, each covers 1280 elems
#pragma unroll
        for (int which = 0; which < 4; which++) {
            const float* W = (which == 0) ? Wq : (which == 1) ? Wk : (which == 2) ? Wv : Wo;
            for (int i = lt; i < 1280; i += 256) {
                int idx = blk * 1280 + i;
                float v = W[idx];
                __half h, l;
                split_h(v, h, l);
                g_w_h[which * WSZ + idx] = h;
                g_w_l[which * WSZ + idx] = l;
            }
        }
        return;
    }
    int c0 = blockIdx.x * 32, x0 = blockIdx.y * 32, t = z;
    if (blockIdx.x == 0 && blockIdx.y == 0 && t == 0) {
        for (int c = lt; c < C_DIM; c += 256) {
            __half h, l;
            split_h(reg[c], h, l);
            g_ctx_h[c] = h;
            g_ctx_l[c] = l;
        }
    }
#pragma unroll
    for (int j = 0; j < 32; j += 8)
        tile[threadIdx.y + j][threadIdx.x] =
            feat[((size_t)(t * C_DIM + c0 + threadIdx.y + j)) * 256 + x0 + threadIdx.x];
    __syncthreads();
#pragma unroll
    for (int j = 0; j < 32; j += 8) {
        float v = tile[threadIdx.x][threadIdx.y + j];
        __half h, l;
        split_h(v, h, l);
        size_t off = (size_t)(1 + t * 256 + x0 + threadIdx.y + j) * C_DIM + c0 + threadIdx.x;
        g_ctx_h[off] = h;
        g_ctx_l[off] = l;
    }
}

// ---------------- kernel 3: fused QKV projection, fp16 HMMA ----------------
__global__ void __launch_bounds__(256) qkv_hmma_kernel() {
    __shared__ __half sAh[128 * 40], sAl[128 * 40];
    __shared__ __half sBh[32 * 72],  sBl[32 * 72];

    int by = blockIdx.y;
    int z = by / 5;
    int rows = (z == 0) ? L_Q : L_CTX;
    int ashift = (z == 0) ? 1 : 0;
    int row0 = blockIdx.x * 128;
    if (row0 >= rows) return;
    int ncol0 = (by % 5) * 64;

    int tid = threadIdx.x;
    int w = tid >> 5, lane = tid & 31;
    int g = lane >> 2, qc = lane & 3;
    int wrow = w * 16;

    uint32_t sAhb = (uint32_t)__cvta_generic_to_shared(sAh);
    uint32_t sAlb = (uint32_t)__cvta_generic_to_shared(sAl);
    uint32_t sBhb = (uint32_t)__cvta_generic_to_shared(sBh);
    uint32_t sBlb = (uint32_t)__cvta_generic_to_shared(sBl);

    float acc[8][4] = {};

    for (int k0 = 0; k0 < C_DIM; k0 += 32) {
        __syncthreads();
#pragma unroll
        for (int i = 0; i < 2; i++) {
            int id = tid + i * 256;
            int r = id >> 2, c = (id & 3) * 8;
            uint4 vh = make_uint4(0, 0, 0, 0), vl = vh;
            if (row0 + r < rows) {
                size_t off = (size_t)(row0 + r + ashift) * C_DIM + k0 + c;
                vh = *(const uint4*)&g_ctx_h[off];
                vl = *(const uint4*)&g_ctx_l[off];
            }
            *(uint4*)&sAh[r * 40 + c] = vh;
            *(uint4*)&sAl[r * 40 + c] = vl;
        }
        {
            int r = tid >> 3, c = (tid & 7) * 8;
            size_t off = (size_t)z * WSZ + (size_t)(k0 + r) * C_DIM + ncol0 + c;
            *(uint4*)&sBh[r * 72 + c] = *(const uint4*)&g_w_h[off];
            *(uint4*)&sBl[r * 72 + c] = *(const uint4*)&g_w_l[off];
        }
        __syncthreads();

#pragma unroll
        for (int kk = 0; kk < 2; kk++) {
            uint32_t ah[4], al[4];
            uint32_t aoff = (uint32_t)(((wrow + (lane & 15)) * 40 + kk * 16 + ((lane >> 4) << 3)) * 2);
            ldsm4(ah, sAhb + aoff);
            ldsm4(al, sAlb + aoff);
#pragma unroll
            for (int nt = 0; nt < 8; nt++) {
                uint32_t bh[2], bl[2];
                uint32_t boff = (uint32_t)(((kk * 16 + (lane & 15)) * 72 + nt * 8) * 2);
                ldsm2t(bh, sBhb + boff);
                ldsm2t(bl, sBlb + boff);
                mma16816(acc[nt], ah, bh);
                mma16816(acc[nt], ah, bl);
                mma16816(acc[nt], al, bh);
            }
        }
    }

    float scale = (z == 0) ? (rsqrtf((float)DHEAD) * LOG2E) : 1.0f;
    __half* out = (z == 0) ? g_q : ((z == 1) ? g_k : g_v);
    int r0 = row0 + wrow + g;
    int r1 = r0 + 8;
#pragma unroll
    for (int nt = 0; nt < 8; nt++) {
        int col = ncol0 + nt * 8 + qc * 2;
        int hh = col / DHEAD;
        int d = col - hh * DHEAD;
        if (r0 < rows) {
            out[((size_t)hh * rows + r0) * DPAD + d]     = __float2half(acc[nt][0] * scale);
            out[((size_t)hh * rows + r0) * DPAD + d + 1] = __float2half(acc[nt][1] * scale);
        }
        if (r1 < rows) {
            out[((size_t)hh * rows + r1) * DPAD + d]     = __float2half(acc[nt][2] * scale);
            out[((size_t)hh * rows + r1) * DPAD + d + 1] = __float2half(acc[nt][3] * scale);
        }
    }
}

// ---------------- kernel 4: flash attention (identical to R12 best) ----------------
#define FLASH_SMEM 61440
__global__ void __launch_bounds__(256, 2) flash_kernel() {
    extern __shared__ __half dsm[];
    __half* sQ     = dsm;                    // 128*56 halfs
    __half* sKbase = dsm + 7168;             // 3 stages * 3584 halfs
    __half* sVbase = dsm + 7168 + 3 * 3584;
    uint4*  sLUT   = (uint4*)(dsm + 28672);  // 256 entries * 16B

    int qb = blockIdx.x, h = blockIdx.y;
    int q0 = qb * 128;
    int tid = threadIdx.x;
    int w = tid >> 5, lane = tid & 31;
    int g = lane >> 2, qc = lane & 3;

    const __half* qg = g_q + (size_t)h * L_Q * DPAD;
    const __half* kg = g_k + (size_t)h * L_CTX * DPAD;
    const __half* vg = g_v + (size_t)h * L_CTX * DPAD;

    uint32_t sK0 = (uint32_t)__cvta_generic_to_shared(sKbase);
    uint32_t sV0 = (uint32_t)__cvta_generic_to_shared(sVbase);

    if (tid < 256) {
        uint32_t e0 = ((tid & 1)   ? 0xFFFFu : 0u) | ((tid & 2)   ? 0xFFFF0000u : 0u);
        uint32_t e1 = ((tid & 4)   ? 0xFFFFu : 0u) | ((tid & 8)   ? 0xFFFF0000u : 0u);
        uint32_t e2 = ((tid & 16)  ? 0xFFFFu : 0u) | ((tid & 32)  ? 0xFFFF0000u : 0u);
        uint32_t e3 = ((tid & 64)  ? 0xFFFFu : 0u) | ((tid & 128) ? 0xFFFF0000u : 0u);
        sLUT[tid] = make_uint4(e0, e1, e2, e3);
    }

    // issue K/V stages 0 and 1
#pragma unroll
    for (int st = 0; st < 2; st++) {
        uint32_t ob = (uint32_t)(st * 7168);
#pragma unroll
        for (int i = 0; i < 3; i++) {
            int id = tid + i * 256;
            int cid = (id < 384) ? id : id - 384;
            int r = cid / 6, p = cid - r * 6;
            const __half* src = (id < 384) ? kg : vg;
            uint32_t dstb = ((id < 384) ? sK0 : sV0) + ob;
            cp_async16(dstb + (uint32_t)((r * 56 + p * 8) * 2),
                       src + (size_t)(1 + st * 64 + r) * DPAD + p * 8);
        }
        asm volatile("cp.async.commit_group;");
    }

    // Q tile
    for (int idx = tid; idx < 128 * 6; idx += 256) {
        int r = idx / 6, p = idx - r * 6;
        *(uint4*)&sQ[r * 56 + p * 8] =
            *(const uint4*)&qg[(size_t)(q0 + r) * DPAD + p * 8];
    }
    __syncthreads();

    // Q fragments: 2x k16 + 1x k8 (dims 32..39)
    uint32_t aQ[2][4], aQ8[2];
    uint32_t sQb = (uint32_t)__cvta_generic_to_shared(sQ);
    int wrow = w * 16;
#pragma unroll
    for (int kk = 0; kk < 2; kk++) {
        uint32_t addr = sQb +
            (uint32_t)(((wrow + (lane & 15)) * 56 + kk * 16 + ((lane >> 4) << 3)) * 2);
        ldsm4(aQ[kk], addr);
    }
    {
        uint32_t addr = sQb + (uint32_t)(((wrow + (lane & 15)) * 56 + 32) * 2);
        ldsm2(aQ8, addr);
    }

    int r0 = wrow + g;
    int r1 = r0 + 8;

    // register token: p_reg = exp2(s_reg) (q pre-scaled by scale*log2e)
    float s0 = 0.f, s1 = 0.f;
#pragma unroll
    for (int d = 0; d < DHEAD; d++) {
        float kd = __half2float(kg[d]);
        s0 += __half2float(qg[(size_t)(q0 + r0) * DPAD + d]) * kd;
        s1 += __half2float(qg[(size_t)(q0 + r1) * DPAD + d]) * kd;
    }
    float pr0f = ex2f(s0), pr1f = ex2f(s1);

    // O accum: 5 n-tiles (dims 0..39) f32 master; l in registers
    float o[5][4];
#pragma unroll
    for (int v = 0; v < 5; v++) {
        float v0 = __half2float(vg[v * 8 + qc * 2]);
        float v1 = __half2float(vg[v * 8 + qc * 2 + 1]);
        o[v][0] = pr0f * v0; o[v][1] = pr0f * v1;
        o[v][2] = pr1f * v0; o[v][3] = pr1f * v1;
    }
    float lac0 = 0.f, lac1 = 0.f;

    const uint16_t* mrow0 = (const uint16_t*)(g_mbits + (size_t)(q0 + r0) * 128);
    const uint16_t* mrow1 = (const uint16_t*)(g_mbits + (size_t)(q0 + r1) * 128);

    for (int t = 0; t < 64; t++) {
        if (t < 63) asm volatile("cp.async.wait_group 1;");
        else        asm volatile("cp.async.wait_group 0;");
        __syncthreads();

        // prefetch stage t+2
        if (t + 2 < 64) {
            int st = t + 2;
            uint32_t ob = (uint32_t)((st % 3) * 7168);
#pragma unroll
            for (int i = 0; i < 3; i++) {
                int id = tid + i * 256;
                int cid = (id < 384) ? id : id - 384;
                int r = cid / 6, p = cid - r * 6;
                const __half* src = (id < 384) ? kg : vg;
                uint32_t dstb = ((id < 384) ? sK0 : sV0) + ob;
                cp_async16(dstb + (uint32_t)((r * 56 + p * 8) * 2),
                           src + (size_t)(1 + st * 64 + r) * DPAD + p * 8);
            }
            asm volatile("cp.async.commit_group;");
        }

        uint32_t sKb = sK0 + (uint32_t)((t % 3) * 7168);
        uint32_t sVb = sV0 + (uint32_t)((t % 3) * 7168);

        uint32_t b16_0 = mrow0[t * 4 + qc];
        uint32_t b16_1 = mrow1[t * 4 + qc];

        // ---- S = Q K^T (f16 accumulators, zero init): 2x k16 + 1x k8 ----
        uint32_t sd[8][2];
#pragma unroll
        for (int v = 0; v < 8; v++) { sd[v][0] = 0u; sd[v][1] = 0u; }
#pragma unroll
        for (int kk = 0; kk < 2; kk++) {
#pragma unroll
            for (int pr = 0; pr < 4; pr++) {
                uint32_t b[4];
                uint32_t addr = sKb +
                    (uint32_t)(((pr * 16 + (lane & 15)) * 56 + kk * 16 + ((lane >> 4) << 3)) * 2);
                ldsm4(b, addr);
                uint32_t b0[2] = {b[0], b[2]};
                uint32_t b1[2] = {b[1], b[3]};
                mma16816_f16(sd[2 * pr],     aQ[kk], b0);
                mma16816_f16(sd[2 * pr + 1], aQ[kk], b1);
            }
        }
#pragma unroll
        for (int pr = 0; pr < 4; pr++) {
            uint32_t b2[2];
            uint32_t addr = sKb +
                (uint32_t)(((pr * 16 + (lane & 15)) * 56 + 32) * 2);
            ldsm2(b2, addr);
            mma16808_f16(sd[2 * pr],     aQ8, b2[0]);
            mma16808_f16(sd[2 * pr + 1], aQ8, b2[1]);
        }

        uint4 mA0 = sLUT[b16_0 & 255], mB0 = sLUT[b16_0 >> 8];
        uint4 mA1 = sLUT[b16_1 & 255], mB1 = sLUT[b16_1 >> 8];

        // ---- P = exp2(S), then zero masked entries ----
#pragma unroll
        for (int v = 0; v < 8; v++) {
            sd[v][0] = hexp2_u(sd[v][0]);
            sd[v][1] = hexp2_u(sd[v][1]);
        }
        sd[0][0] &= mA0.x; sd[1][0] &= mA0.y; sd[2][0] &= mA0.z; sd[3][0] &= mA0.w;
        sd[4][0] &= mB0.x; sd[5][0] &= mB0.y; sd[6][0] &= mB0.z; sd[7][0] &= mB0.w;
        sd[0][1] &= mA1.x; sd[1][1] &= mA1.y; sd[2][1] &= mA1.z; sd[3][1] &= mA1.w;
        sd[4][1] &= mB1.x; sd[5][1] &= mB1.y; sd[6][1] &= mB1.z; sd[7][1] &= mB1.w;

        // ---- l partial sums: fp16 tree -> f32 ----
        {
            __half2 t0 = __hadd2(__hadd2(__hadd2(u2h(sd[0][0]), u2h(sd[1][0])),
                                         __hadd2(u2h(sd[2][0]), u2h(sd[3][0]))),
                                 __hadd2(__hadd2(u2h(sd[4][0]), u2h(sd[5][0])),
                                         __hadd2(u2h(sd[6][0]), u2h(sd[7][0]))));
            float2 f0 = __half22float2(t0);
            lac0 += f0.x + f0.y;
            __half2 t1 = __hadd2(__hadd2(__hadd2(u2h(sd[0][1]), u2h(sd[1][1])),
                                         __hadd2(u2h(sd[2][1]), u2h(sd[3][1]))),
                                 __hadd2(__hadd2(u2h(sd[4][1]), u2h(sd[5][1])),
                                         __hadd2(u2h(sd[6][1]), u2h(sd[7][1]))));
            float2 f1 = __half22float2(t1);
            lac1 += f1.x + f1.y;
        }

        // ---- O_tile = P V in f16 accum (5 n-tiles), promoted to f32 once ----
        uint32_t od[5][2];
#pragma unroll
        for (int v = 0; v < 5; v++) { od[v][0] = 0u; od[v][1] = 0u; }
#pragma unroll
        for (int kk = 0; kk < 4; kk++) {
            uint32_t pa[4] = {sd[2 * kk][0], sd[2 * kk][1],
                              sd[2 * kk + 1][0], sd[2 * kk + 1][1]};
            {
                uint32_t b[4];
                uint32_t addr = sVb +
                    (uint32_t)(((kk * 16 + (lane & 15)) * 56 + ((lane >> 4) << 3)) * 2);
                ldsm4t(b, addr);
                uint32_t t0[2] = {b[0], b[1]};
                uint32_t t1[2] = {b[2], b[3]};
                mma16816_f16(od[0], pa, t0);
                mma16816_f16(od[1], pa, t1);
            }
            {
                uint32_t b[4];
                uint32_t addr = sVb +
                    (uint32_t)(((kk * 16 + (lane & 15)) * 56 + 16 + ((lane >> 4) << 3)) * 2);
                ldsm4t(b, addr);
                uint32_t t2[2] = {b[0], b[1]};
                uint32_t t3[2] = {b[2], b[3]};
                mma16816_f16(od[2], pa, t2);
                mma16816_f16(od[3], pa, t3);
            }
            {
                uint32_t b[2];
                uint32_t addr = sVb +
                    (uint32_t)(((kk * 16 + (lane & 15)) * 56 + 32) * 2);
                ldsm2t(b, addr);
                mma16816_f16(od[4], pa, b);
            }
        }
#pragma unroll
        for (int v = 0; v < 5; v++) {
            float2 f0 = __half22float2(u2h(od[v][0]));
            float2 f1 = __half22float2(u2h(od[v][1]));
            o[v][0] += f0.x; o[v][1] += f0.y;
            o[v][2] += f1.x; o[v][3] += f1.y;
        }
    }

    // ---- epilogue ----
    lac0 += __shfl_xor_sync(0xffffffffu, lac0, 1);
    lac0 += __shfl_xor_sync(0xffffffffu, lac0, 2);
    lac1 += __shfl_xor_sync(0xffffffffu, lac1, 1);
    lac1 += __shfl_xor_sync(0xffffffffu, lac1, 2);
    float inv0 = 1.f / (lac0 + pr0f);
    float inv1 = 1.f / (lac1 + pr1f);

    __half* ogh = g_oh + (size_t)q0 * C_DIM + h * DHEAD;
    __half* ogl = g_ol + (size_t)q0 * C_DIM + h * DHEAD;
#pragma unroll
    for (int v = 0; v < 5; v++) {
        int n = v * 8 + qc * 2;
        float f00 = o[v][0] * inv0, f01 = o[v][1] * inv0;
        float f10 = o[v][2] * inv1, f11 = o[v][3] * inv1;
        __half h00, l00, h01, l01, h10, l10, h11, l11;
        split_h(f00, h00, l00); split_h(f01, h01, l01);
        split_h(f10, h10, l10); split_h(f11, h11, l11);
        *(__half2*)&ogh[(size_t)r0 * C_DIM + n] = __halves2half2(h00, h01);
        *(__half2*)&ogl[(size_t)r0 * C_DIM + n] = __halves2half2(l00, l01);
        *(__half2*)&ogh[(size_t)r1 * C_DIM + n] = __halves2half2(h10, h11);
        *(__half2*)&ogl[(size_t)r1 * C_DIM + n] = __halves2half2(l10, l11);
    }
}

// ---------------- kernel 5: output projection, fp16 HMMA ----------------
__global__ void __launch_bounds__(256) out_hmma_kernel(const float* __restrict__ bo,
                                                       float* __restrict__ out) {
    __shared__ __half sAh[128 * 40], sAl[128 * 40];
    __shared__ __half sBh[32 * 72],  sBl[32 * 72];

    int row0 = blockIdx.x * 128;
    int ncol0 = blockIdx.y * 64;

    int tid = threadIdx.x;
    int w = tid >> 5, lane = tid & 31;
    int g = lane >> 2, qc = lane & 3;
    int wrow = w * 16;

    uint32_t sAhb = (uint32_t)__cvta_generic_to_shared(sAh);
    uint32_t sAlb = (uint32_t)__cvta_generic_to_shared(sAl);
    uint32_t sBhb = (uint32_t)__cvta_generic_to_shared(sBh);
    uint32_t sBlb = (uint32_t)__cvta_generic_to_shared(sBl);

    float acc[8][4] = {};

    for (int k0 = 0; k0 < C_DIM; k0 += 32) {
        __syncthreads();
#pragma unroll
        for (int i = 0; i < 2; i++) {
            int id = tid + i * 256;
            int r = id >> 2, c = (id & 3) * 8;
            size_t off = (size_t)(row0 + r) * C_DIM + k0 + c;
            *(uint4*)&sAh[r * 40 + c] = *(const uint4*)&g_oh[off];
            *(uint4*)&sAl[r * 40 + c] = *(const uint4*)&g_ol[off];
        }
        {
            int r = tid >> 3, c = (tid & 7) * 8;
            size_t off = (size_t)3 * WSZ + (size_t)(k0 + r) * C_DIM + ncol0 + c;
            *(uint4*)&sBh[r * 72 + c] = *(const uint4*)&g_w_h[off];
            *(uint4*)&sBl[r * 72 + c] = *(const uint4*)&g_w_l[off];
        }
        __syncthreads();

#pragma unroll
        for (int kk = 0; kk < 2; kk++) {
            uint32_t ah[4], al[4];
            uint32_t aoff = (uint32_t)(((wrow + (lane & 15)) * 40 + kk * 16 + ((lane >> 4) << 3)) * 2);
            ldsm4(ah, sAhb + aoff);
            ldsm4(al, sAlb + aoff);
#pragma unroll
            for (int nt = 0; nt < 8; nt++) {
                uint32_t bh[2], bl[2];
                uint32_t boff = (uint32_t)(((kk * 16 + (lane & 15)) * 72 + nt * 8) * 2);
                ldsm2t(bh, sBhb + boff);
                ldsm2t(bl, sBlb + boff);
                mma16816(acc[nt], ah, bh);
                mma16816(acc[nt], ah, bl);
                mma16816(acc[nt], al, bh);
            }
        }
    }

    int r0 = row0 + wrow + g;
    int r1 = r0 + 8;
    int p0 = (r0 & 255) * 16 + (r0 >> 8);
    int p1 = (r1 & 255) * 16 + (r1 >> 8);
#pragma unroll
    for (int nt = 0; nt < 8; nt++) {
        int col = ncol0 + nt * 8 + qc * 2;
        float b0 = bo[col], b1 = bo[col + 1];
        *(float2*)&out[(size_t)p0 * C_DIM + col] =
            make_float2(acc[nt][0] + b0, acc[nt][1] + b1);
        *(float2*)&out[(size_t)p1 * C_DIM + col] =
            make_float2(acc[nt][2] + b0, acc[nt][3] + b1);
    }
}

// ---------------- launch ----------------
extern "C" void kernel_launch(void* const* d_in, const int* in_sizes, int n_in,
                              void* d_out, int out_size) {
    const float* feat         = (const float*)d_in[0];
    const unsigned char* mask = (const unsigned char*)d_in[1];
    const float* Wq           = (const float*)d_in[2];
    const float* Wk           = (const float*)d_in[3];
    const float* Wv           = (const float*)d_in[4];
    const float* reg          = (const float*)d_in[5];
    const float* Wo           = (const float*)d_in[6];
    const float* bo           = (const float*)d_in[7];
    float* out                = (float*)d_out;

    (void)in_sizes; (void)n_in; (void)out_size;

    pack_mask_kernel<<<65536, 256>>>(mask);
    prep_kernel<<<dim3(10, 8, 17), dim3(32, 8)>>>(feat, reg, Wq, Wk, Wv, Wo);
    qkv_hmma_kernel<<<dim3(33, 15), 256>>>();

    cudaFuncSetAttribute(flash_kernel,
                         cudaFuncAttributeMaxDynamicSharedMemorySize, FLASH_SMEM);
    flash_kernel<<<dim3(32, N_HEADS), 256, FLASH_SMEM>>>();

    out_hmma_kernel<<<dim3(32, 5), 256>>>(bo, out);
}

// round 16
// speedup vs baseline: 1.1541x; 1.1299x over previous
#include <cuda_runtime.h>
#include <cuda_fp16.h>
#include <cstdint>

#define L_Q   4096
#define L_CTX 4097
#define C_DIM 320
#define N_HEADS 8
#define DHEAD 40
#define DPAD  48
#define WSZ   (C_DIM * C_DIM)   // 102400

// ---------------- device scratch (no allocations allowed) ----------------
__device__ __half g_ctx_h[(size_t)L_CTX * C_DIM];
__device__ __half g_ctx_l[(size_t)L_CTX * C_DIM];
__device__ __half g_w_h[4 * WSZ];
__device__ __half g_w_l[4 * WSZ];
__device__ __half g_q[(size_t)N_HEADS * L_Q * DPAD];    // d 40..47 zero
__device__ __half g_k[(size_t)N_HEADS * L_CTX * DPAD];
__device__ __half g_v[(size_t)N_HEADS * L_CTX * DPAD];
__device__ __half g_oh[(size_t)L_Q * C_DIM];
__device__ __half g_ol[(size_t)L_Q * C_DIM];
__device__ unsigned g_mbits[(size_t)L_Q * 128];         // fragment-order packed mask bits

#define LOG2E 1.4426950408889634f

// ---------------- helpers ----------------
__device__ __forceinline__ void mma16816(float* d, const uint32_t* a, const uint32_t* b) {
    asm volatile(
        "mma.sync.aligned.m16n8k16.row.col.f32.f16.f16.f32 "
        "{%0,%1,%2,%3}, {%4,%5,%6,%7}, {%8,%9}, {%0,%1,%2,%3};"
        : "+f"(d[0]), "+f"(d[1]), "+f"(d[2]), "+f"(d[3])
        : "r"(a[0]), "r"(a[1]), "r"(a[2]), "r"(a[3]), "r"(b[0]), "r"(b[1]));
}
__device__ __forceinline__ void mma16816_f16(uint32_t* d, const uint32_t* a, const uint32_t* b) {
    asm volatile(
        "mma.sync.aligned.m16n8k16.row.col.f16.f16.f16.f16 "
        "{%0,%1}, {%2,%3,%4,%5}, {%6,%7}, {%0,%1};"
        : "+r"(d[0]), "+r"(d[1])
        : "r"(a[0]), "r"(a[1]), "r"(a[2]), "r"(a[3]), "r"(b[0]), "r"(b[1]));
}
__device__ __forceinline__ void mma16808_f16(uint32_t* d, const uint32_t* a, uint32_t b) {
    asm volatile(
        "mma.sync.aligned.m16n8k8.row.col.f16.f16.f16.f16 "
        "{%0,%1}, {%2,%3}, {%4}, {%0,%1};"
        : "+r"(d[0]), "+r"(d[1])
        : "r"(a[0]), "r"(a[1]), "r"(b));
}
__device__ __forceinline__ void ldsm4(uint32_t* r, uint32_t saddr) {
    asm volatile("ldmatrix.sync.aligned.m8n8.x4.shared.b16 {%0,%1,%2,%3}, [%4];"
                 : "=r"(r[0]), "=r"(r[1]), "=r"(r[2]), "=r"(r[3]) : "r"(saddr));
}
__device__ __forceinline__ void ldsm2(uint32_t* r, uint32_t saddr) {
    asm volatile("ldmatrix.sync.aligned.m8n8.x2.shared.b16 {%0,%1}, [%2];"
                 : "=r"(r[0]), "=r"(r[1]) : "r"(saddr));
}
__device__ __forceinline__ void ldsm2t(uint32_t* r, uint32_t saddr) {
    asm volatile("ldmatrix.sync.aligned.m8n8.x2.trans.shared.b16 {%0,%1}, [%2];"
                 : "=r"(r[0]), "=r"(r[1]) : "r"(saddr));
}
__device__ __forceinline__ void ldsm4t(uint32_t* r, uint32_t saddr) {
    asm volatile("ldmatrix.sync.aligned.m8n8.x4.trans.shared.b16 {%0,%1,%2,%3}, [%4];"
                 : "=r"(r[0]), "=r"(r[1]), "=r"(r[2]), "=r"(r[3]) : "r"(saddr));
}
__device__ __forceinline__ void split_h(float v, __half& h, __half& l) {
    h = __float2half_rn(v);
    l = __float2half_rn(v - __half2float(h));
}
__device__ __forceinline__ float ex2f(float x) {
    float y; asm("ex2.approx.f32 %0, %1;" : "=f"(y) : "f"(x)); return y;
}
__device__ __forceinline__ uint32_t hexp2_u(uint32_t x) {
    uint32_t y; asm("ex2.approx.f16x2 %0, %1;" : "=r"(y) : "r"(x)); return y;
}
__device__ __forceinline__ __half2 u2h(uint32_t u) { return *(__half2*)&u; }
__device__ __forceinline__ void cp_async16(uint32_t dst, const void* src) {
    asm volatile("cp.async.cg.shared.global [%0], [%1], 16;" :: "r"(dst), "l"(src));
}

// ---------------- kernel 1: pack mask bits (smem-staged, coalesced) ----------------
__global__ void pack_mask_kernel(const void* __restrict__ mask) {
    __shared__ unsigned char f[2][4096];
    int tid = threadIdx.x;
    int lane = tid & 31, w = tid >> 5;
    int row0 = blockIdx.x * 2;

    unsigned probe = ((const unsigned*)mask)[lane];
    bool is_u8 = __any_sync(0xffffffffu, probe > 1u);

    if (!is_u8) {
        const int4* src = (const int4*)((const int*)mask + (size_t)row0 * 4096);
#pragma unroll
        for (int i = 0; i < 8; i++) {
            int id = tid + i * 256;
            int4 v = src[id];
            int base = id * 4;
            f[base >> 12][base & 4095]       = (unsigned char)(v.x != 0);
            f[base >> 12][(base & 4095) + 1] = (unsigned char)(v.y != 0);
            f[base >> 12][(base & 4095) + 2] = (unsigned char)(v.z != 0);
            f[base >> 12][(base & 4095) + 3] = (unsigned char)(v.w != 0);
        }
    } else {
        const uint4* src = (const uint4*)((const unsigned char*)mask + (size_t)row0 * 4096);
#pragma unroll
        for (int i = 0; i < 2; i++) {
            int id = tid + i * 256;
            uint4 v = src[id];
            int base = id * 16;
            unsigned char* dst = &f[base >> 12][base & 4095];
            uint32_t ws[4] = {v.x, v.y, v.z, v.w};
#pragma unroll
            for (int jj = 0; jj < 4; jj++)
#pragma unroll
                for (int b = 0; b < 4; b++)
                    dst[jj * 4 + b] = (unsigned char)(((ws[jj] >> (b * 8)) & 255u) != 0);
        }
    }
    __syncthreads();

    for (int i = 0; i < 32; i++) {
        int u = w * 32 + i;
        int r = u >> 7;
        int rem = u & 127;
        int t = rem >> 1, half = rem & 1;
        int qc = half * 2 + (lane >> 4);
        int v = (lane >> 1) & 7, j = lane & 1;
        int col = t * 64 + v * 8 + qc * 2 + j;
        unsigned bal = __ballot_sync(0xffffffffu, f[r][col] != 0);
        if (lane == 0) g_mbits[(size_t)(row0 + r) * 128 + rem] = bal;
    }
}

// ---------------- kernel 2: prep = build context + split weights ----------------
__global__ void prep_kernel(const float* __restrict__ feat, const float* __restrict__ reg,
                            const float* __restrict__ Wq, const float* __restrict__ Wk,
                            const float* __restrict__ Wv, const float* __restrict__ Wo) {
    __shared__ float tile[32][33];
    int z = blockIdx.z;
    int lt = threadIdx.y * 32 + threadIdx.x;
    if (z == 16) {
        int blk = blockIdx.y * 10 + blockIdx.x;
#pragma unroll
        for (int which = 0; which < 4; which++) {
            const float* W = (which == 0) ? Wq : (which == 1) ? Wk : (which == 2) ? Wv : Wo;
            for (int i = lt; i < 1280; i += 256) {
                int idx = blk * 1280 + i;
                float v = W[idx];
                __half h, l;
                split_h(v, h, l);
                g_w_h[which * WSZ + idx] = h;
                g_w_l[which * WSZ + idx] = l;
            }
        }
        return;
    }
    int c0 = blockIdx.x * 32, x0 = blockIdx.y * 32, t = z;
    if (blockIdx.x == 0 && blockIdx.y == 0 && t == 0) {
        for (int c = lt; c < C_DIM; c += 256) {
            __half h, l;
            split_h(reg[c], h, l);
            g_ctx_h[c] = h;
            g_ctx_l[c] = l;
        }
    }
#pragma unroll
    for (int j = 0; j < 32; j += 8)
        tile[threadIdx.y + j][threadIdx.x] =
            feat[((size_t)(t * C_DIM + c0 + threadIdx.y + j)) * 256 + x0 + threadIdx.x];
    __syncthreads();
#pragma unroll
    for (int j = 0; j < 32; j += 8) {
        float v = tile[threadIdx.x][threadIdx.y + j];
        __half h, l;
        split_h(v, h, l);
        size_t off = (size_t)(1 + t * 256 + x0 + threadIdx.y + j) * C_DIM + c0 + threadIdx.x;
        g_ctx_h[off] = h;
        g_ctx_l[off] = l;
    }
}

// ---------------- kernel 3: fused QKV projection, fp16 HMMA ----------------
__global__ void __launch_bounds__(256) qkv_hmma_kernel() {
    __shared__ __half sAh[128 * 40], sAl[128 * 40];
    __shared__ __half sBh[32 * 72],  sBl[32 * 72];

    int by = blockIdx.y;
    int z = by / 5;
    int rows = (z == 0) ? L_Q : L_CTX;
    int ashift = (z == 0) ? 1 : 0;
    int row0 = blockIdx.x * 128;
    if (row0 >= rows) return;
    int ncol0 = (by % 5) * 64;

    int tid = threadIdx.x;
    int w = tid >> 5, lane = tid & 31;
    int g = lane >> 2, qc = lane & 3;
    int wrow = w * 16;

    uint32_t sAhb = (uint32_t)__cvta_generic_to_shared(sAh);
    uint32_t sAlb = (uint32_t)__cvta_generic_to_shared(sAl);
    uint32_t sBhb = (uint32_t)__cvta_generic_to_shared(sBh);
    uint32_t sBlb = (uint32_t)__cvta_generic_to_shared(sBl);

    float acc[8][4] = {};

    for (int k0 = 0; k0 < C_DIM; k0 += 32) {
        __syncthreads();
#pragma unroll
        for (int i = 0; i < 2; i++) {
            int id = tid + i * 256;
            int r = id >> 2, c = (id & 3) * 8;
            uint4 vh = make_uint4(0, 0, 0, 0), vl = vh;
            if (row0 + r < rows) {
                size_t off = (size_t)(row0 + r + ashift) * C_DIM + k0 + c;
                vh = *(const uint4*)&g_ctx_h[off];
                vl = *(const uint4*)&g_ctx_l[off];
            }
            *(uint4*)&sAh[r * 40 + c] = vh;
            *(uint4*)&sAl[r * 40 + c] = vl;
        }
        {
            int r = tid >> 3, c = (tid & 7) * 8;
            size_t off = (size_t)z * WSZ + (size_t)(k0 + r) * C_DIM + ncol0 + c;
            *(uint4*)&sBh[r * 72 + c] = *(const uint4*)&g_w_h[off];
            *(uint4*)&sBl[r * 72 + c] = *(const uint4*)&g_w_l[off];
        }
        __syncthreads();

#pragma unroll
        for (int kk = 0; kk < 2; kk++) {
            uint32_t ah[4], al[4];
            uint32_t aoff = (uint32_t)(((wrow + (lane & 15)) * 40 + kk * 16 + ((lane >> 4) << 3)) * 2);
            ldsm4(ah, sAhb + aoff);
            ldsm4(al, sAlb + aoff);
#pragma unroll
            for (int nt = 0; nt < 8; nt++) {
                uint32_t bh[2], bl[2];
                uint32_t boff = (uint32_t)(((kk * 16 + (lane & 15)) * 72 + nt * 8) * 2);
                ldsm2t(bh, sBhb + boff);
                ldsm2t(bl, sBlb + boff);
                mma16816(acc[nt], ah, bh);
                mma16816(acc[nt], ah, bl);
                mma16816(acc[nt], al, bh);
            }
        }
    }

    float scale = (z == 0) ? (rsqrtf((float)DHEAD) * LOG2E) : 1.0f;
    __half* out = (z == 0) ? g_q : ((z == 1) ? g_k : g_v);
    int r0 = row0 + wrow + g;
    int r1 = r0 + 8;
#pragma unroll
    for (int nt = 0; nt < 8; nt++) {
        int col = ncol0 + nt * 8 + qc * 2;
        int hh = col / DHEAD;
        int d = col - hh * DHEAD;
        if (r0 < rows) {
            out[((size_t)hh * rows + r0) * DPAD + d]     = __float2half(acc[nt][0] * scale);
            out[((size_t)hh * rows + r0) * DPAD + d + 1] = __float2half(acc[nt][1] * scale);
        }
        if (r1 < rows) {
            out[((size_t)hh * rows + r1) * DPAD + d]     = __float2half(acc[nt][2] * scale);
            out[((size_t)hh * rows + r1) * DPAD + d + 1] = __float2half(acc[nt][3] * scale);
        }
    }
}

// ---------------- kernel 4: flash attention (R13-exact: 64 tiles, in-kernel normalize) ----------------
#define FLASH_SMEM 61440
__global__ void __launch_bounds__(256, 2) flash_kernel() {
    extern __shared__ __half dsm[];
    __half* sQ     = dsm;
    __half* sKbase = dsm + 7168;
    __half* sVbase = dsm + 7168 + 3 * 3584;
    uint4*  sLUT   = (uint4*)(dsm + 28672);

    int qb = blockIdx.x, h = blockIdx.y;
    int q0 = qb * 128;
    int tid = threadIdx.x;
    int w = tid >> 5, lane = tid & 31;
    int g = lane >> 2, qc = lane & 3;

    const __half* qg = g_q + (size_t)h * L_Q * DPAD;
    const __half* kg = g_k + (size_t)h * L_CTX * DPAD;
    const __half* vg = g_v + (size_t)h * L_CTX * DPAD;

    uint32_t sK0 = (uint32_t)__cvta_generic_to_shared(sKbase);
    uint32_t sV0 = (uint32_t)__cvta_generic_to_shared(sVbase);

    if (tid < 256) {
        uint32_t e0 = ((tid & 1)   ? 0xFFFFu : 0u) | ((tid & 2)   ? 0xFFFF0000u : 0u);
        uint32_t e1 = ((tid & 4)   ? 0xFFFFu : 0u) | ((tid & 8)   ? 0xFFFF0000u : 0u);
        uint32_t e2 = ((tid & 16)  ? 0xFFFFu : 0u) | ((tid & 32)  ? 0xFFFF0000u : 0u);
        uint32_t e3 = ((tid & 64)  ? 0xFFFFu : 0u) | ((tid & 128) ? 0xFFFF0000u : 0u);
        sLUT[tid] = make_uint4(e0, e1, e2, e3);
    }

#pragma unroll
    for (int st = 0; st < 2; st++) {
        uint32_t ob = (uint32_t)(st * 7168);
#pragma unroll
        for (int i = 0; i < 3; i++) {
            int id = tid + i * 256;
            int cid = (id < 384) ? id : id - 384;
            int r = cid / 6, p = cid - r * 6;
            const __half* src = (id < 384) ? kg : vg;
            uint32_t dstb = ((id < 384) ? sK0 : sV0) + ob;
            cp_async16(dstb + (uint32_t)((r * 56 + p * 8) * 2),
                       src + (size_t)(1 + st * 64 + r) * DPAD + p * 8);
        }
        asm volatile("cp.async.commit_group;");
    }

    for (int idx = tid; idx < 128 * 6; idx += 256) {
        int r = idx / 6, p = idx - r * 6;
        *(uint4*)&sQ[r * 56 + p * 8] =
            *(const uint4*)&qg[(size_t)(q0 + r) * DPAD + p * 8];
    }
    __syncthreads();

    uint32_t aQ[2][4], aQ8[2];
    uint32_t sQb = (uint32_t)__cvta_generic_to_shared(sQ);
    int wrow = w * 16;
#pragma unroll
    for (int kk = 0; kk < 2; kk++) {
        uint32_t addr = sQb +
            (uint32_t)(((wrow + (lane & 15)) * 56 + kk * 16 + ((lane >> 4) << 3)) * 2);
        ldsm4(aQ[kk], addr);
    }
    {
        uint32_t addr = sQb + (uint32_t)(((wrow + (lane & 15)) * 56 + 32) * 2);
        ldsm2(aQ8, addr);
    }

    int r0 = wrow + g;
    int r1 = r0 + 8;

    float s0 = 0.f, s1 = 0.f;
#pragma unroll
    for (int d = 0; d < DHEAD; d++) {
        float kd = __half2float(kg[d]);
        s0 += __half2float(qg[(size_t)(q0 + r0) * DPAD + d]) * kd;
        s1 += __half2float(qg[(size_t)(q0 + r1) * DPAD + d]) * kd;
    }
    float pr0f = ex2f(s0), pr1f = ex2f(s1);

    float o[5][4];
#pragma unroll
    for (int v = 0; v < 5; v++) {
        float v0 = __half2float(vg[v * 8 + qc * 2]);
        float v1 = __half2float(vg[v * 8 + qc * 2 + 1]);
        o[v][0] = pr0f * v0; o[v][1] = pr0f * v1;
        o[v][2] = pr1f * v0; o[v][3] = pr1f * v1;
    }
    float lac0 = 0.f, lac1 = 0.f;

    const uint16_t* mrow0 = (const uint16_t*)(g_mbits + (size_t)(q0 + r0) * 128);
    const uint16_t* mrow1 = (const uint16_t*)(g_mbits + (size_t)(q0 + r1) * 128);

    for (int t = 0; t < 64; t++) {
        if (t < 63) asm volatile("cp.async.wait_group 1;");
        else        asm volatile("cp.async.wait_group 0;");
        __syncthreads();

        if (t + 2 < 64) {
            int st = t + 2;
            uint32_t ob = (uint32_t)((st % 3) * 7168);
#pragma unroll
            for (int i = 0; i < 3; i++) {
                int id = tid + i * 256;
                int cid = (id < 384) ? id : id - 384;
                int r = cid / 6, p = cid - r * 6;
                const __half* src = (id < 384) ? kg : vg;
                uint32_t dstb = ((id < 384) ? sK0 : sV0) + ob;
                cp_async16(dstb + (uint32_t)((r * 56 + p * 8) * 2),
                           src + (size_t)(1 + st * 64 + r) * DPAD + p * 8);
            }
            asm volatile("cp.async.commit_group;");
        }

        uint32_t sKb = sK0 + (uint32_t)((t % 3) * 7168);
        uint32_t sVb = sV0 + (uint32_t)((t % 3) * 7168);

        uint32_t b16_0 = mrow0[t * 4 + qc];
        uint32_t b16_1 = mrow1[t * 4 + qc];

        // ---- S = Q K^T (f16 accum): 2x k16 + 1x k8 ----
        uint32_t sd[8][2];
#pragma unroll
        for (int v = 0; v < 8; v++) { sd[v][0] = 0u; sd[v][1] = 0u; }
#pragma unroll
        for (int kk = 0; kk < 2; kk++) {
#pragma unroll
            for (int pr = 0; pr < 4; pr++) {
                uint32_t b[4];
                uint32_t addr = sKb +
                    (uint32_t)(((pr * 16 + (lane & 15)) * 56 + kk * 16 + ((lane >> 4) << 3)) * 2);
                ldsm4(b, addr);
                uint32_t b0[2] = {b[0], b[2]};
                uint32_t b1[2] = {b[1], b[3]};
                mma16816_f16(sd[2 * pr],     aQ[kk], b0);
                mma16816_f16(sd[2 * pr + 1], aQ[kk], b1);
            }
        }
#pragma unroll
        for (int pr = 0; pr < 4; pr++) {
            uint32_t b2[2];
            uint32_t addr = sKb +
                (uint32_t)(((pr * 16 + (lane & 15)) * 56 + 32) * 2);
            ldsm2(b2, addr);
            mma16808_f16(sd[2 * pr],     aQ8, b2[0]);
            mma16808_f16(sd[2 * pr + 1], aQ8, b2[1]);
        }

        uint4 mA0 = sLUT[b16_0 & 255], mB0 = sLUT[b16_0 >> 8];
        uint4 mA1 = sLUT[b16_1 & 255], mB1 = sLUT[b16_1 >> 8];

        // ---- P = exp2(S), mask ----
#pragma unroll
        for (int v = 0; v < 8; v++) {
            sd[v][0] = hexp2_u(sd[v][0]);
            sd[v][1] = hexp2_u(sd[v][1]);
        }
        sd[0][0] &= mA0.x; sd[1][0] &= mA0.y; sd[2][0] &= mA0.z; sd[3][0] &= mA0.w;
        sd[4][0] &= mB0.x; sd[5][0] &= mB0.y; sd[6][0] &= mB0.z; sd[7][0] &= mB0.w;
        sd[0][1] &= mA1.x; sd[1][1] &= mA1.y; sd[2][1] &= mA1.z; sd[3][1] &= mA1.w;
        sd[4][1] &= mB1.x; sd[5][1] &= mB1.y; sd[6][1] &= mB1.z; sd[7][1] &= mB1.w;

        // ---- l partial sums: fp16 tree -> f32 ----
        {
            __half2 t0 = __hadd2(__hadd2(__hadd2(u2h(sd[0][0]), u2h(sd[1][0])),
                                         __hadd2(u2h(sd[2][0]), u2h(sd[3][0]))),
                                 __hadd2(__hadd2(u2h(sd[4][0]), u2h(sd[5][0])),
                                         __hadd2(u2h(sd[6][0]), u2h(sd[7][0]))));
            float2 f0 = __half22float2(t0);
            lac0 += f0.x + f0.y;
            __half2 t1 = __hadd2(__hadd2(__hadd2(u2h(sd[0][1]), u2h(sd[1][1])),
                                         __hadd2(u2h(sd[2][1]), u2h(sd[3][1]))),
                                 __hadd2(__hadd2(u2h(sd[4][1]), u2h(sd[5][1])),
                                         __hadd2(u2h(sd[6][1]), u2h(sd[7][1]))));
            float2 f1 = __half22float2(t1);
            lac1 += f1.x + f1.y;
        }

        // ---- O_tile = P V in f16 accum (5 n-tiles), promoted to f32 once ----
        uint32_t od[5][2];
#pragma unroll
        for (int v = 0; v < 5; v++) { od[v][0] = 0u; od[v][1] = 0u; }
#pragma unroll
        for (int kk = 0; kk < 4; kk++) {
            uint32_t pa[4] = {sd[2 * kk][0], sd[2 * kk][1],
                              sd[2 * kk + 1][0], sd[2 * kk + 1][1]};
            {
                uint32_t b[4];
                uint32_t addr = sVb +
                    (uint32_t)(((kk * 16 + (lane & 15)) * 56 + ((lane >> 4) << 3)) * 2);
                ldsm4t(b, addr);
                uint32_t t0[2] = {b[0], b[1]};
                uint32_t t1[2] = {b[2], b[3]};
                mma16816_f16(od[0], pa, t0);
                mma16816_f16(od[1], pa, t1);
            }
            {
                uint32_t b[4];
                uint32_t addr = sVb +
                    (uint32_t)(((kk * 16 + (lane & 15)) * 56 + 16 + ((lane >> 4) << 3)) * 2);
                ldsm4t(b, addr);
                uint32_t t2[2] = {b[0], b[1]};
                uint32_t t3[2] = {b[2], b[3]};
                mma16816_f16(od[2], pa, t2);
                mma16816_f16(od[3], pa, t3);
            }
            {
                uint32_t b[2];
                uint32_t addr = sVb +
                    (uint32_t)(((kk * 16 + (lane & 15)) * 56 + 32) * 2);
                ldsm2t(b, addr);
                mma16816_f16(od[4], pa, b);
            }
        }
#pragma unroll
        for (int v = 0; v < 5; v++) {
            float2 f0 = __half22float2(u2h(od[v][0]));
            float2 f1 = __half22float2(u2h(od[v][1]));
            o[v][0] += f0.x; o[v][1] += f0.y;
            o[v][2] += f1.x; o[v][3] += f1.y;
        }
    }

    // ---- epilogue ----
    lac0 += __shfl_xor_sync(0xffffffffu, lac0, 1);
    lac0 += __shfl_xor_sync(0xffffffffu, lac0, 2);
    lac1 += __shfl_xor_sync(0xffffffffu, lac1, 1);
    lac1 += __shfl_xor_sync(0xffffffffu, lac1, 2);
    float inv0 = 1.f / (lac0 + pr0f);
    float inv1 = 1.f / (lac1 + pr1f);

    __half* ogh = g_oh + (size_t)q0 * C_DIM + h * DHEAD;
    __half* ogl = g_ol + (size_t)q0 * C_DIM + h * DHEAD;
#pragma unroll
    for (int v = 0; v < 5; v++) {
        int n = v * 8 + qc * 2;
        float f00 = o[v][0] * inv0, f01 = o[v][1] * inv0;
        float f10 = o[v][2] * inv1, f11 = o[v][3] * inv1;
        __half h00, l00, h01, l01, h10, l10, h11, l11;
        split_h(f00, h00, l00); split_h(f01, h01, l01);
        split_h(f10, h10, l10); split_h(f11, h11, l11);
        *(__half2*)&ogh[(size_t)r0 * C_DIM + n] = __halves2half2(h00, h01);
        *(__half2*)&ogl[(size_t)r0 * C_DIM + n] = __halves2half2(l00, l01);
        *(__half2*)&ogh[(size_t)r1 * C_DIM + n] = __halves2half2(h10, h11);
        *(__half2*)&ogl[(size_t)r1 * C_DIM + n] = __halves2half2(l10, l11);
    }
}

// ---------------- kernel 5: output projection, fp16 HMMA (R13-exact) ----------------
__global__ void __launch_bounds__(256) out_hmma_kernel(const float* __restrict__ bo,
                                                       float* __restrict__ out) {
    __shared__ __half sAh[128 * 40], sAl[128 * 40];
    __shared__ __half sBh[32 * 72],  sBl[32 * 72];

    int row0 = blockIdx.x * 128;
    int ncol0 = blockIdx.y * 64;

    int tid = threadIdx.x;
    int w = tid >> 5, lane = tid & 31;
    int g = lane >> 2, qc = lane & 3;
    int wrow = w * 16;

    uint32_t sAhb = (uint32_t)__cvta_generic_to_shared(sAh);
    uint32_t sAlb = (uint32_t)__cvta_generic_to_shared(sAl);
    uint32_t sBhb = (uint32_t)__cvta_generic_to_shared(sBh);
    uint32_t sBlb = (uint32_t)__cvta_generic_to_shared(sBl);

    float acc[8][4] = {};

    for (int k0 = 0; k0 < C_DIM; k0 += 32) {
        __syncthreads();
#pragma unroll
        for (int i = 0; i < 2; i++) {
            int id = tid + i * 256;
            int r = id >> 2, c = (id & 3) * 8;
            size_t off = (size_t)(row0 + r) * C_DIM + k0 + c;
            *(uint4*)&sAh[r * 40 + c] = *(const uint4*)&g_oh[off];
            *(uint4*)&sAl[r * 40 + c] = *(const uint4*)&g_ol[off];
        }
        {
            int r = tid >> 3, c = (tid & 7) * 8;
            size_t off = (size_t)3 * WSZ + (size_t)(k0 + r) * C_DIM + ncol0 + c;
            *(uint4*)&sBh[r * 72 + c] = *(const uint4*)&g_w_h[off];
            *(uint4*)&sBl[r * 72 + c] = *(const uint4*)&g_w_l[off];
        }
        __syncthreads();

#pragma unroll
        for (int kk = 0; kk < 2; kk++) {
            uint32_t ah[4], al[4];
            uint32_t aoff = (uint32_t)(((wrow + (lane & 15)) * 40 + kk * 16 + ((lane >> 4) << 3)) * 2);
            ldsm4(ah, sAhb + aoff);
            ldsm4(al, sAlb + aoff);
#pragma unroll
            for (int nt = 0; nt < 8; nt++) {
                uint32_t bh[2], bl[2];
                uint32_t boff = (uint32_t)(((kk * 16 + (lane & 15)) * 72 + nt * 8) * 2);
                ldsm2t(bh, sBhb + boff);
                ldsm2t(bl, sBlb + boff);
                mma16816(acc[nt], ah, bh);
                mma16816(acc[nt], ah, bl);
                mma16816(acc[nt], al, bh);
            }
        }
    }

    int r0 = row0 + wrow + g;
    int r1 = r0 + 8;
    int p0 = (r0 & 255) * 16 + (r0 >> 8);
    int p1 = (r1 & 255) * 16 + (r1 >> 8);
#pragma unroll
    for (int nt = 0; nt < 8; nt++) {
        int col = ncol0 + nt * 8 + qc * 2;
        float b0 = bo[col], b1 = bo[col + 1];
        *(float2*)&out[(size_t)p0 * C_DIM + col] =
            make_float2(acc[nt][0] + b0, acc[nt][1] + b1);
        *(float2*)&out[(size_t)p1 * C_DIM + col] =
            make_float2(acc[nt][2] + b0, acc[nt][3] + b1);
    }
}

// ---------------- launch ----------------
extern "C" void kernel_launch(void* const* d_in, const int* in_sizes, int n_in,
                              void* d_out, int out_size) {
    const float* feat         = (const float*)d_in[0];
    const unsigned char* mask = (const unsigned char*)d_in[1];
    const float* Wq           = (const float*)d_in[2];
    const float* Wk           = (const float*)d_in[3];
    const float* Wv           = (const float*)d_in[4];
    const float* reg          = (const float*)d_in[5];
    const float* Wo           = (const float*)d_in[6];
    const float* bo           = (const float*)d_in[7];
    float* out                = (float*)d_out;

    (void)in_sizes; (void)n_in; (void)out_size;

    pack_mask_kernel<<<2048, 256>>>(mask);
    prep_kernel<<<dim3(10, 8, 17), dim3(32, 8)>>>(feat, reg, Wq, Wk, Wv, Wo);
    qkv_hmma_kernel<<<dim3(33, 15), 256>>>();

    cudaFuncSetAttribute(flash_kernel,
                         cudaFuncAttributeMaxDynamicSharedMemorySize, FLASH_SMEM);
    flash_kernel<<<dim3(32, N_HEADS), 256, FLASH_SMEM>>>();

    out_hmma_kernel<<<dim3(32, 5), 256>>>(bo, out);
}

// round 17
// speedup vs baseline: 1.1856x; 1.0272x over previous
#include <cuda_runtime.h>
#include <cuda_fp16.h>
#include <cstdint>

#define L_Q   4096
#define L_CTX 4097
#define C_DIM 320
#define N_HEADS 8
#define DHEAD 40
#define DPAD  48
#define WSZ   (C_DIM * C_DIM)   // 102400

// ---------------- device scratch (no allocations allowed) ----------------
__device__ __half g_ctx_h[(size_t)L_CTX * C_DIM];
__device__ __half g_ctx_l[(size_t)L_CTX * C_DIM];
__device__ __half g_w_h[4 * WSZ];
__device__ __half g_w_l[4 * WSZ];
__device__ __half g_q[(size_t)N_HEADS * L_Q * DPAD];    // d 40..47 zero
__device__ __half g_k[(size_t)N_HEADS * L_CTX * DPAD];
__device__ __half g_v[(size_t)N_HEADS * L_CTX * DPAD];
__device__ __half g_oh[(size_t)L_Q * C_DIM];
__device__ __half g_ol[(size_t)L_Q * C_DIM];
__device__ unsigned g_mbits[(size_t)L_Q * 128];         // fragment-order packed mask bits

#define LOG2E 1.4426950408889634f

// ---------------- helpers ----------------
__device__ __forceinline__ void mma16816(float* d, const uint32_t* a, const uint32_t* b) {
    asm volatile(
        "mma.sync.aligned.m16n8k16.row.col.f32.f16.f16.f32 "
        "{%0,%1,%2,%3}, {%4,%5,%6,%7}, {%8,%9}, {%0,%1,%2,%3};"
        : "+f"(d[0]), "+f"(d[1]), "+f"(d[2]), "+f"(d[3])
        : "r"(a[0]), "r"(a[1]), "r"(a[2]), "r"(a[3]), "r"(b[0]), "r"(b[1]));
}
__device__ __forceinline__ void mma16816_f16(uint32_t* d, const uint32_t* a, const uint32_t* b) {
    asm volatile(
        "mma.sync.aligned.m16n8k16.row.col.f16.f16.f16.f16 "
        "{%0,%1}, {%2,%3,%4,%5}, {%6,%7}, {%0,%1};"
        : "+r"(d[0]), "+r"(d[1])
        : "r"(a[0]), "r"(a[1]), "r"(a[2]), "r"(a[3]), "r"(b[0]), "r"(b[1]));
}
__device__ __forceinline__ void mma16808_f16(uint32_t* d, const uint32_t* a, uint32_t b) {
    asm volatile(
        "mma.sync.aligned.m16n8k8.row.col.f16.f16.f16.f16 "
        "{%0,%1}, {%2,%3}, {%4}, {%0,%1};"
        : "+r"(d[0]), "+r"(d[1])
        : "r"(a[0]), "r"(a[1]), "r"(b));
}
__device__ __forceinline__ void ldsm4(uint32_t* r, uint32_t saddr) {
    asm volatile("ldmatrix.sync.aligned.m8n8.x4.shared.b16 {%0,%1,%2,%3}, [%4];"
                 : "=r"(r[0]), "=r"(r[1]), "=r"(r[2]), "=r"(r[3]) : "r"(saddr));
}
__device__ __forceinline__ void ldsm2(uint32_t* r, uint32_t saddr) {
    asm volatile("ldmatrix.sync.aligned.m8n8.x2.shared.b16 {%0,%1}, [%2];"
                 : "=r"(r[0]), "=r"(r[1]) : "r"(saddr));
}
__device__ __forceinline__ void ldsm2t(uint32_t* r, uint32_t saddr) {
    asm volatile("ldmatrix.sync.aligned.m8n8.x2.trans.shared.b16 {%0,%1}, [%2];"
                 : "=r"(r[0]), "=r"(r[1]) : "r"(saddr));
}
__device__ __forceinline__ void ldsm4t(uint32_t* r, uint32_t saddr) {
    asm volatile("ldmatrix.sync.aligned.m8n8.x4.trans.shared.b16 {%0,%1,%2,%3}, [%4];"
                 : "=r"(r[0]), "=r"(r[1]), "=r"(r[2]), "=r"(r[3]) : "r"(saddr));
}
__device__ __forceinline__ void split_h(float v, __half& h, __half& l) {
    h = __float2half_rn(v);
    l = __float2half_rn(v - __half2float(h));
}
__device__ __forceinline__ float ex2f(float x) {
    float y; asm("ex2.approx.f32 %0, %1;" : "=f"(y) : "f"(x)); return y;
}
__device__ __forceinline__ uint32_t hexp2_u(uint32_t x) {
    uint32_t y; asm("ex2.approx.f16x2 %0, %1;" : "=r"(y) : "r"(x)); return y;
}
__device__ __forceinline__ __half2 u2h(uint32_t u) { return *(__half2*)&u; }
__device__ __forceinline__ void cp_async16(uint32_t dst, const void* src) {
    asm volatile("cp.async.cg.shared.global [%0], [%1], 16;" :: "r"(dst), "l"(src));
}

// ---------------- kernel 1: pack mask bits (smem-staged, coalesced) ----------------
__global__ void pack_mask_kernel(const void* __restrict__ mask) {
    __shared__ unsigned char f[2][4096];
    int tid = threadIdx.x;
    int lane = tid & 31, w = tid >> 5;
    int row0 = blockIdx.x * 2;

    unsigned probe = ((const unsigned*)mask)[lane];
    bool is_u8 = __any_sync(0xffffffffu, probe > 1u);

    if (!is_u8) {
        const int4* src = (const int4*)((const int*)mask + (size_t)row0 * 4096);
#pragma unroll
        for (int i = 0; i < 8; i++) {
            int id = tid + i * 256;
            int4 v = src[id];
            int base = id * 4;
            f[base >> 12][base & 4095]       = (unsigned char)(v.x != 0);
            f[base >> 12][(base & 4095) + 1] = (unsigned char)(v.y != 0);
            f[base >> 12][(base & 4095) + 2] = (unsigned char)(v.z != 0);
            f[base >> 12][(base & 4095) + 3] = (unsigned char)(v.w != 0);
        }
    } else {
        const uint4* src = (const uint4*)((const unsigned char*)mask + (size_t)row0 * 4096);
#pragma unroll
        for (int i = 0; i < 2; i++) {
            int id = tid + i * 256;
            uint4 v = src[id];
            int base = id * 16;
            unsigned char* dst = &f[base >> 12][base & 4095];
            uint32_t ws[4] = {v.x, v.y, v.z, v.w};
#pragma unroll
            for (int jj = 0; jj < 4; jj++)
#pragma unroll
                for (int b = 0; b < 4; b++)
                    dst[jj * 4 + b] = (unsigned char)(((ws[jj] >> (b * 8)) & 255u) != 0);
        }
    }
    __syncthreads();

    for (int i = 0; i < 32; i++) {
        int u = w * 32 + i;
        int r = u >> 7;
        int rem = u & 127;
        int t = rem >> 1, half = rem & 1;
        int qc = half * 2 + (lane >> 4);
        int v = (lane >> 1) & 7, j = lane & 1;
        int col = t * 64 + v * 8 + qc * 2 + j;
        unsigned bal = __ballot_sync(0xffffffffu, f[r][col] != 0);
        if (lane == 0) g_mbits[(size_t)(row0 + r) * 128 + rem] = bal;
    }
}

// ---------------- kernel 2: prep = build context + split weights ----------------
__global__ void prep_kernel(const float* __restrict__ feat, const float* __restrict__ reg,
                            const float* __restrict__ Wq, const float* __restrict__ Wk,
                            const float* __restrict__ Wv, const float* __restrict__ Wo) {
    __shared__ float tile[32][33];
    int z = blockIdx.z;
    int lt = threadIdx.y * 32 + threadIdx.x;
    if (z == 16) {
        int blk = blockIdx.y * 10 + blockIdx.x;
#pragma unroll
        for (int which = 0; which < 4; which++) {
            const float* W = (which == 0) ? Wq : (which == 1) ? Wk : (which == 2) ? Wv : Wo;
            for (int i = lt; i < 1280; i += 256) {
                int idx = blk * 1280 + i;
                float v = W[idx];
                __half h, l;
                split_h(v, h, l);
                g_w_h[which * WSZ + idx] = h;
                g_w_l[which * WSZ + idx] = l;
            }
        }
        return;
    }
    int c0 = blockIdx.x * 32, x0 = blockIdx.y * 32, t = z;
    if (blockIdx.x == 0 && blockIdx.y == 0 && t == 0) {
        for (int c = lt; c < C_DIM; c += 256) {
            __half h, l;
            split_h(reg[c], h, l);
            g_ctx_h[c] = h;
            g_ctx_l[c] = l;
        }
    }
#pragma unroll
    for (int j = 0; j < 32; j += 8)
        tile[threadIdx.y + j][threadIdx.x] =
            feat[((size_t)(t * C_DIM + c0 + threadIdx.y + j)) * 256 + x0 + threadIdx.x];
    __syncthreads();
#pragma unroll
    for (int j = 0; j < 32; j += 8) {
        float v = tile[threadIdx.x][threadIdx.y + j];
        __half h, l;
        split_h(v, h, l);
        size_t off = (size_t)(1 + t * 256 + x0 + threadIdx.y + j) * C_DIM + c0 + threadIdx.x;
        g_ctx_h[off] = h;
        g_ctx_l[off] = l;
    }
}

// ---------------- kernel 3: fused QKV projection, fp16 HMMA ----------------
__global__ void __launch_bounds__(256) qkv_hmma_kernel() {
    __shared__ __half sAh[128 * 40], sAl[128 * 40];
    __shared__ __half sBh[32 * 72],  sBl[32 * 72];

    int by = blockIdx.y;
    int z = by / 5;
    int rows = (z == 0) ? L_Q : L_CTX;
    int ashift = (z == 0) ? 1 : 0;
    int row0 = blockIdx.x * 128;
    if (row0 >= rows) return;
    int ncol0 = (by % 5) * 64;

    int tid = threadIdx.x;
    int w = tid >> 5, lane = tid & 31;
    int g = lane >> 2, qc = lane & 3;
    int wrow = w * 16;

    uint32_t sAhb = (uint32_t)__cvta_generic_to_shared(sAh);
    uint32_t sAlb = (uint32_t)__cvta_generic_to_shared(sAl);
    uint32_t sBhb = (uint32_t)__cvta_generic_to_shared(sBh);
    uint32_t sBlb = (uint32_t)__cvta_generic_to_shared(sBl);

    float acc[8][4] = {};

    for (int k0 = 0; k0 < C_DIM; k0 += 32) {
        __syncthreads();
#pragma unroll
        for (int i = 0; i < 2; i++) {
            int id = tid + i * 256;
            int r = id >> 2, c = (id & 3) * 8;
            uint4 vh = make_uint4(0, 0, 0, 0), vl = vh;
            if (row0 + r < rows) {
                size_t off = (size_t)(row0 + r + ashift) * C_DIM + k0 + c;
                vh = *(const uint4*)&g_ctx_h[off];
                vl = *(const uint4*)&g_ctx_l[off];
            }
            *(uint4*)&sAh[r * 40 + c] = vh;
            *(uint4*)&sAl[r * 40 + c] = vl;
        }
        {
            int r = tid >> 3, c = (tid & 7) * 8;
            size_t off = (size_t)z * WSZ + (size_t)(k0 + r) * C_DIM + ncol0 + c;
            *(uint4*)&sBh[r * 72 + c] = *(const uint4*)&g_w_h[off];
            *(uint4*)&sBl[r * 72 + c] = *(const uint4*)&g_w_l[off];
        }
        __syncthreads();

#pragma unroll
        for (int kk = 0; kk < 2; kk++) {
            uint32_t ah[4], al[4];
            uint32_t aoff = (uint32_t)(((wrow + (lane & 15)) * 40 + kk * 16 + ((lane >> 4) << 3)) * 2);
            ldsm4(ah, sAhb + aoff);
            ldsm4(al, sAlb + aoff);
#pragma unroll
            for (int nt = 0; nt < 8; nt++) {
                uint32_t bh[2], bl[2];
                uint32_t boff = (uint32_t)(((kk * 16 + (lane & 15)) * 72 + nt * 8) * 2);
                ldsm2t(bh, sBhb + boff);
                ldsm2t(bl, sBlb + boff);
                mma16816(acc[nt], ah, bh);
                mma16816(acc[nt], ah, bl);
                mma16816(acc[nt], al, bh);
            }
        }
    }

    float scale = (z == 0) ? (rsqrtf((float)DHEAD) * LOG2E) : 1.0f;
    __half* out = (z == 0) ? g_q : ((z == 1) ? g_k : g_v);
    int r0 = row0 + wrow + g;
    int r1 = r0 + 8;
#pragma unroll
    for (int nt = 0; nt < 8; nt++) {
        int col = ncol0 + nt * 8 + qc * 2;
        int hh = col / DHEAD;
        int d = col - hh * DHEAD;
        if (r0 < rows) {
            out[((size_t)hh * rows + r0) * DPAD + d]     = __float2half(acc[nt][0] * scale);
            out[((size_t)hh * rows + r0) * DPAD + d + 1] = __float2half(acc[nt][1] * scale);
        }
        if (r1 < rows) {
            out[((size_t)hh * rows + r1) * DPAD + d]     = __float2half(acc[nt][2] * scale);
            out[((size_t)hh * rows + r1) * DPAD + d + 1] = __float2half(acc[nt][3] * scale);
        }
    }
}

// ---------------- kernel 4: flash attention — 4 warps x 32 q-rows ----------------
// Each K/V ldsm fragment now feeds TWO 16-row mma tiles: smem traffic per row
// halves. Per-row arithmetic order identical to R16 (same tiles, same order).
#define FLASH_SMEM 61440
__global__ void __launch_bounds__(128, 2) flash_kernel() {
    extern __shared__ __half dsm[];
    __half* sQ     = dsm;                    // 128*56 halfs
    __half* sKbase = dsm + 7168;             // 3 stages * 3584 halfs
    __half* sVbase = dsm + 7168 + 3 * 3584;
    uint4*  sLUT   = (uint4*)(dsm + 28672);  // 256 entries * 16B

    int qb = blockIdx.x, h = blockIdx.y;
    int q0 = qb * 128;
    int tid = threadIdx.x;
    int w = tid >> 5, lane = tid & 31;
    int g = lane >> 2, qc = lane & 3;
    int wrow = w * 32;

    const __half* qg = g_q + (size_t)h * L_Q * DPAD;
    const __half* kg = g_k + (size_t)h * L_CTX * DPAD;
    const __half* vg = g_v + (size_t)h * L_CTX * DPAD;

    uint32_t sK0 = (uint32_t)__cvta_generic_to_shared(sKbase);
    uint32_t sV0 = (uint32_t)__cvta_generic_to_shared(sVbase);

    for (int i = tid; i < 256; i += 128) {
        uint32_t e0 = ((i & 1)   ? 0xFFFFu : 0u) | ((i & 2)   ? 0xFFFF0000u : 0u);
        uint32_t e1 = ((i & 4)   ? 0xFFFFu : 0u) | ((i & 8)   ? 0xFFFF0000u : 0u);
        uint32_t e2 = ((i & 16)  ? 0xFFFFu : 0u) | ((i & 32)  ? 0xFFFF0000u : 0u);
        uint32_t e3 = ((i & 64)  ? 0xFFFFu : 0u) | ((i & 128) ? 0xFFFF0000u : 0u);
        sLUT[i] = make_uint4(e0, e1, e2, e3);
    }

    // issue K/V stages 0 and 1 (768 chunks each: K 0..383, V 384..767)
#pragma unroll
    for (int st = 0; st < 2; st++) {
        uint32_t ob = (uint32_t)(st * 7168);
#pragma unroll
        for (int i = 0; i < 6; i++) {
            int id = tid + i * 128;
            int cid = (id < 384) ? id : id - 384;
            int r = cid / 6, p = cid - r * 6;
            const __half* src = (id < 384) ? kg : vg;
            uint32_t dstb = ((id < 384) ? sK0 : sV0) + ob;
            cp_async16(dstb + (uint32_t)((r * 56 + p * 8) * 2),
                       src + (size_t)(1 + st * 64 + r) * DPAD + p * 8);
        }
        asm volatile("cp.async.commit_group;");
    }

    // Q tile (768 uint4)
    for (int idx = tid; idx < 128 * 6; idx += 128) {
        int r = idx / 6, p = idx - r * 6;
        *(uint4*)&sQ[r * 56 + p * 8] =
            *(const uint4*)&qg[(size_t)(q0 + r) * DPAD + p * 8];
    }
    __syncthreads();

    // Q fragments for two 16-row tiles: A = rows wrow.., B = rows wrow+16..
    uint32_t aQA[2][4], aQB[2][4], aQA8[2], aQB8[2];
    uint32_t sQb = (uint32_t)__cvta_generic_to_shared(sQ);
#pragma unroll
    for (int kk = 0; kk < 2; kk++) {
        ldsm4(aQA[kk], sQb +
            (uint32_t)(((wrow + (lane & 15)) * 56 + kk * 16 + ((lane >> 4) << 3)) * 2));
        ldsm4(aQB[kk], sQb +
            (uint32_t)(((wrow + 16 + (lane & 15)) * 56 + kk * 16 + ((lane >> 4) << 3)) * 2));
    }
    ldsm2(aQA8, sQb + (uint32_t)(((wrow + (lane & 15)) * 56 + 32) * 2));
    ldsm2(aQB8, sQb + (uint32_t)(((wrow + 16 + (lane & 15)) * 56 + 32) * 2));

    int r0 = wrow + g, r1 = r0 + 8, r2 = r0 + 16, r3 = r0 + 24;

    // register token: p = exp2(s) for 4 rows (q pre-scaled by scale*log2e)
    float s0 = 0.f, s1 = 0.f, s2 = 0.f, s3 = 0.f;
#pragma unroll
    for (int d = 0; d < DHEAD; d++) {
        float kd = __half2float(kg[d]);
        s0 += __half2float(qg[(size_t)(q0 + r0) * DPAD + d]) * kd;
        s1 += __half2float(qg[(size_t)(q0 + r1) * DPAD + d]) * kd;
        s2 += __half2float(qg[(size_t)(q0 + r2) * DPAD + d]) * kd;
        s3 += __half2float(qg[(size_t)(q0 + r3) * DPAD + d]) * kd;
    }
    float pr0f = ex2f(s0), pr1f = ex2f(s1), pr2f = ex2f(s2), pr3f = ex2f(s3);

    float oA[5][4], oB[5][4];
#pragma unroll
    for (int v = 0; v < 5; v++) {
        float v0 = __half2float(vg[v * 8 + qc * 2]);
        float v1 = __half2float(vg[v * 8 + qc * 2 + 1]);
        oA[v][0] = pr0f * v0; oA[v][1] = pr0f * v1;
        oA[v][2] = pr1f * v0; oA[v][3] = pr1f * v1;
        oB[v][0] = pr2f * v0; oB[v][1] = pr2f * v1;
        oB[v][2] = pr3f * v0; oB[v][3] = pr3f * v1;
    }
    float lac0 = 0.f, lac1 = 0.f, lac2 = 0.f, lac3 = 0.f;

    const uint16_t* mrow0 = (const uint16_t*)(g_mbits + (size_t)(q0 + r0) * 128);
    const uint16_t* mrow1 = (const uint16_t*)(g_mbits + (size_t)(q0 + r1) * 128);
    const uint16_t* mrow2 = (const uint16_t*)(g_mbits + (size_t)(q0 + r2) * 128);
    const uint16_t* mrow3 = (const uint16_t*)(g_mbits + (size_t)(q0 + r3) * 128);

    for (int t = 0; t < 64; t++) {
        if (t < 63) asm volatile("cp.async.wait_group 1;");
        else        asm volatile("cp.async.wait_group 0;");
        __syncthreads();

        if (t + 2 < 64) {
            int st = t + 2;
            uint32_t ob = (uint32_t)((st % 3) * 7168);
#pragma unroll
            for (int i = 0; i < 6; i++) {
                int id = tid + i * 128;
                int cid = (id < 384) ? id : id - 384;
                int r = cid / 6, p = cid - r * 6;
                const __half* src = (id < 384) ? kg : vg;
                uint32_t dstb = ((id < 384) ? sK0 : sV0) + ob;
                cp_async16(dstb + (uint32_t)((r * 56 + p * 8) * 2),
                           src + (size_t)(1 + st * 64 + r) * DPAD + p * 8);
            }
            asm volatile("cp.async.commit_group;");
        }

        uint32_t sKb = sK0 + (uint32_t)((t % 3) * 7168);
        uint32_t sVb = sV0 + (uint32_t)((t % 3) * 7168);

        uint32_t b16_0 = mrow0[t * 4 + qc];
        uint32_t b16_1 = mrow1[t * 4 + qc];
        uint32_t b16_2 = mrow2[t * 4 + qc];
        uint32_t b16_3 = mrow3[t * 4 + qc];

        // ---- S = Q K^T (f16 accum), K fragments shared across both row tiles ----
        uint32_t sdA[8][2], sdB[8][2];
#pragma unroll
        for (int v = 0; v < 8; v++) {
            sdA[v][0] = 0u; sdA[v][1] = 0u;
            sdB[v][0] = 0u; sdB[v][1] = 0u;
        }
#pragma unroll
        for (int kk = 0; kk < 2; kk++) {
#pragma unroll
            for (int pr = 0; pr < 4; pr++) {
                uint32_t b[4];
                uint32_t addr = sKb +
                    (uint32_t)(((pr * 16 + (lane & 15)) * 56 + kk * 16 + ((lane >> 4) << 3)) * 2);
                ldsm4(b, addr);
                uint32_t b0[2] = {b[0], b[2]};
                uint32_t b1[2] = {b[1], b[3]};
                mma16816_f16(sdA[2 * pr],     aQA[kk], b0);
                mma16816_f16(sdA[2 * pr + 1], aQA[kk], b1);
                mma16816_f16(sdB[2 * pr],     aQB[kk], b0);
                mma16816_f16(sdB[2 * pr + 1], aQB[kk], b1);
            }
        }
#pragma unroll
        for (int pr = 0; pr < 4; pr++) {
            uint32_t b2[2];
            uint32_t addr = sKb +
                (uint32_t)(((pr * 16 + (lane & 15)) * 56 + 32) * 2);
            ldsm2(b2, addr);
            mma16808_f16(sdA[2 * pr],     aQA8, b2[0]);
            mma16808_f16(sdA[2 * pr + 1], aQA8, b2[1]);
            mma16808_f16(sdB[2 * pr],     aQB8, b2[0]);
            mma16808_f16(sdB[2 * pr + 1], aQB8, b2[1]);
        }

        uint4 mA0 = sLUT[b16_0 & 255], mB0 = sLUT[b16_0 >> 8];
        uint4 mA1 = sLUT[b16_1 & 255], mB1 = sLUT[b16_1 >> 8];
        uint4 mA2 = sLUT[b16_2 & 255], mB2 = sLUT[b16_2 >> 8];
        uint4 mA3 = sLUT[b16_3 & 255], mB3 = sLUT[b16_3 >> 8];

        // ---- P = exp2(S), mask ----
#pragma unroll
        for (int v = 0; v < 8; v++) {
            sdA[v][0] = hexp2_u(sdA[v][0]);
            sdA[v][1] = hexp2_u(sdA[v][1]);
            sdB[v][0] = hexp2_u(sdB[v][0]);
            sdB[v][1] = hexp2_u(sdB[v][1]);
        }
        sdA[0][0] &= mA0.x; sdA[1][0] &= mA0.y; sdA[2][0] &= mA0.z; sdA[3][0] &= mA0.w;
        sdA[4][0] &= mB0.x; sdA[5][0] &= mB0.y; sdA[6][0] &= mB0.z; sdA[7][0] &= mB0.w;
        sdA[0][1] &= mA1.x; sdA[1][1] &= mA1.y; sdA[2][1] &= mA1.z; sdA[3][1] &= mA1.w;
        sdA[4][1] &= mB1.x; sdA[5][1] &= mB1.y; sdA[6][1] &= mB1.z; sdA[7][1] &= mB1.w;
        sdB[0][0] &= mA2.x; sdB[1][0] &= mA2.y; sdB[2][0] &= mA2.z; sdB[3][0] &= mA2.w;
        sdB[4][0] &= mB2.x; sdB[5][0] &= mB2.y; sdB[6][0] &= mB2.z; sdB[7][0] &= mB2.w;
        sdB[0][1] &= mA3.x; sdB[1][1] &= mA3.y; sdB[2][1] &= mA3.z; sdB[3][1] &= mA3.w;
        sdB[4][1] &= mB3.x; sdB[5][1] &= mB3.y; sdB[6][1] &= mB3.z; sdB[7][1] &= mB3.w;

        // ---- l partial sums: fp16 trees -> f32 ----
        {
            __half2 t0 = __hadd2(__hadd2(__hadd2(u2h(sdA[0][0]), u2h(sdA[1][0])),
                                         __hadd2(u2h(sdA[2][0]), u2h(sdA[3][0]))),
                                 __hadd2(__hadd2(u2h(sdA[4][0]), u2h(sdA[5][0])),
                                         __hadd2(u2h(sdA[6][0]), u2h(sdA[7][0]))));
            float2 f0 = __half22float2(t0);
            lac0 += f0.x + f0.y;
            __half2 t1 = __hadd2(__hadd2(__hadd2(u2h(sdA[0][1]), u2h(sdA[1][1])),
                                         __hadd2(u2h(sdA[2][1]), u2h(sdA[3][1]))),
                                 __hadd2(__hadd2(u2h(sdA[4][1]), u2h(sdA[5][1])),
                                         __hadd2(u2h(sdA[6][1]), u2h(sdA[7][1]))));
            float2 f1 = __half22float2(t1);
            lac1 += f1.x + f1.y;
            __half2 t2 = __hadd2(__hadd2(__hadd2(u2h(sdB[0][0]), u2h(sdB[1][0])),
                                         __hadd2(u2h(sdB[2][0]), u2h(sdB[3][0]))),
                                 __hadd2(__hadd2(u2h(sdB[4][0]), u2h(sdB[5][0])),
                                         __hadd2(u2h(sdB[6][0]), u2h(sdB[7][0]))));
            float2 f2 = __half22float2(t2);
            lac2 += f2.x + f2.y;
            __half2 t3 = __hadd2(__hadd2(__hadd2(u2h(sdB[0][1]), u2h(sdB[1][1])),
                                         __hadd2(u2h(sdB[2][1]), u2h(sdB[3][1]))),
                                 __hadd2(__hadd2(u2h(sdB[4][1]), u2h(sdB[5][1])),
                                         __hadd2(u2h(sdB[6][1]), u2h(sdB[7][1]))));
            float2 f3 = __half22float2(t3);
            lac3 += f3.x + f3.y;
        }

        // ---- O_tile = P V in f16 accum, V fragments shared; promote to f32 ----
        uint32_t odA[5][2], odB[5][2];
#pragma unroll
        for (int v = 0; v < 5; v++) {
            odA[v][0] = 0u; odA[v][1] = 0u;
            odB[v][0] = 0u; odB[v][1] = 0u;
        }
#pragma unroll
        for (int kk = 0; kk < 4; kk++) {
            uint32_t paA[4] = {sdA[2 * kk][0], sdA[2 * kk][1],
                               sdA[2 * kk + 1][0], sdA[2 * kk + 1][1]};
            uint32_t paB[4] = {sdB[2 * kk][0], sdB[2 * kk][1],
                               sdB[2 * kk + 1][0], sdB[2 * kk + 1][1]};
            {
                uint32_t b[4];
                uint32_t addr = sVb +
                    (uint32_t)(((kk * 16 + (lane & 15)) * 56 + ((lane >> 4) << 3)) * 2);
                ldsm4t(b, addr);
                uint32_t t0[2] = {b[0], b[1]};
                uint32_t t1[2] = {b[2], b[3]};
                mma16816_f16(odA[0], paA, t0);
                mma16816_f16(odA[1], paA, t1);
                mma16816_f16(odB[0], paB, t0);
                mma16816_f16(odB[1], paB, t1);
            }
            {
                uint32_t b[4];
                uint32_t addr = sVb +
                    (uint32_t)(((kk * 16 + (lane & 15)) * 56 + 16 + ((lane >> 4) << 3)) * 2);
                ldsm4t(b, addr);
                uint32_t t2[2] = {b[0], b[1]};
                uint32_t t3[2] = {b[2], b[3]};
                mma16816_f16(odA[2], paA, t2);
                mma16816_f16(odA[3], paA, t3);
                mma16816_f16(odB[2], paB, t2);
                mma16816_f16(odB[3], paB, t3);
            }
            {
                uint32_t b[2];
                uint32_t addr = sVb +
                    (uint32_t)(((kk * 16 + (lane & 15)) * 56 + 32) * 2);
                ldsm2t(b, addr);
                mma16816_f16(odA[4], paA, b);
                mma16816_f16(odB[4], paB, b);
            }
        }
#pragma unroll
        for (int v = 0; v < 5; v++) {
            float2 fa0 = __half22float2(u2h(odA[v][0]));
            float2 fa1 = __half22float2(u2h(odA[v][1]));
            oA[v][0] += fa0.x; oA[v][1] += fa0.y;
            oA[v][2] += fa1.x; oA[v][3] += fa1.y;
            float2 fb0 = __half22float2(u2h(odB[v][0]));
            float2 fb1 = __half22float2(u2h(odB[v][1]));
            oB[v][0] += fb0.x; oB[v][1] += fb0.y;
            oB[v][2] += fb1.x; oB[v][3] += fb1.y;
        }
    }

    // ---- epilogue ----
    lac0 += __shfl_xor_sync(0xffffffffu, lac0, 1);
    lac0 += __shfl_xor_sync(0xffffffffu, lac0, 2);
    lac1 += __shfl_xor_sync(0xffffffffu, lac1, 1);
    lac1 += __shfl_xor_sync(0xffffffffu, lac1, 2);
    lac2 += __shfl_xor_sync(0xffffffffu, lac2, 1);
    lac2 += __shfl_xor_sync(0xffffffffu, lac2, 2);
    lac3 += __shfl_xor_sync(0xffffffffu, lac3, 1);
    lac3 += __shfl_xor_sync(0xffffffffu, lac3, 2);
    float inv0 = 1.f / (lac0 + pr0f);
    float inv1 = 1.f / (lac1 + pr1f);
    float inv2 = 1.f / (lac2 + pr2f);
    float inv3 = 1.f / (lac3 + pr3f);

    __half* ogh = g_oh + (size_t)q0 * C_DIM + h * DHEAD;
    __half* ogl = g_ol + (size_t)q0 * C_DIM + h * DHEAD;
#pragma unroll
    for (int v = 0; v < 5; v++) {
        int n = v * 8 + qc * 2;
        float fA00 = oA[v][0] * inv0, fA01 = oA[v][1] * inv0;
        float fA10 = oA[v][2] * inv1, fA11 = oA[v][3] * inv1;
        float fB00 = oB[v][0] * inv2, fB01 = oB[v][1] * inv2;
        float fB10 = oB[v][2] * inv3, fB11 = oB[v][3] * inv3;
        __half hh, ll, hh2, ll2;
        split_h(fA00, hh, ll); split_h(fA01, hh2, ll2);
        *(__half2*)&ogh[(size_t)r0 * C_DIM + n] = __halves2half2(hh, hh2);
        *(__half2*)&ogl[(size_t)r0 * C_DIM + n] = __halves2half2(ll, ll2);
        split_h(fA10, hh, ll); split_h(fA11, hh2, ll2);
        *(__half2*)&ogh[(size_t)r1 * C_DIM + n] = __halves2half2(hh, hh2);
        *(__half2*)&ogl[(size_t)r1 * C_DIM + n] = __halves2half2(ll, ll2);
        split_h(fB00, hh, ll); split_h(fB01, hh2, ll2);
        *(__half2*)&ogh[(size_t)r2 * C_DIM + n] = __halves2half2(hh, hh2);
        *(__half2*)&ogl[(size_t)r2 * C_DIM + n] = __halves2half2(ll, ll2);
        split_h(fB10, hh, ll); split_h(fB11, hh2, ll2);
        *(__half2*)&ogh[(size_t)r3 * C_DIM + n] = __halves2half2(hh, hh2);
        *(__half2*)&ogl[(size_t)r3 * C_DIM + n] = __halves2half2(ll, ll2);
    }
}

// ---------------- kernel 5: output projection, fp16 HMMA ----------------
__global__ void __launch_bounds__(256) out_hmma_kernel(const float* __restrict__ bo,
                                                       float* __restrict__ out) {
    __shared__ __half sAh[128 * 40], sAl[128 * 40];
    __shared__ __half sBh[32 * 72],  sBl[32 * 72];

    int row0 = blockIdx.x * 128;
    int ncol0 = blockIdx.y * 64;

    int tid = threadIdx.x;
    int w = tid >> 5, lane = tid & 31;
    int g = lane >> 2, qc = lane & 3;
    int wrow = w * 16;

    uint32_t sAhb = (uint32_t)__cvta_generic_to_shared(sAh);
    uint32_t sAlb = (uint32_t)__cvta_generic_to_shared(sAl);
    uint32_t sBhb = (uint32_t)__cvta_generic_to_shared(sBh);
    uint32_t sBlb = (uint32_t)__cvta_generic_to_shared(sBl);

    float acc[8][4] = {};

    for (int k0 = 0; k0 < C_DIM; k0 += 32) {
        __syncthreads();
#pragma unroll
        for (int i = 0; i < 2; i++) {
            int id = tid + i * 256;
            int r = id >> 2, c = (id & 3) * 8;
            size_t off = (size_t)(row0 + r) * C_DIM + k0 + c;
            *(uint4*)&sAh[r * 40 + c] = *(const uint4*)&g_oh[off];
            *(uint4*)&sAl[r * 40 + c] = *(const uint4*)&g_ol[off];
        }
        {
            int r = tid >> 3, c = (tid & 7) * 8;
            size_t off = (size_t)3 * WSZ + (size_t)(k0 + r) * C_DIM + ncol0 + c;
            *(uint4*)&sBh[r * 72 + c] = *(const uint4*)&g_w_h[off];
            *(uint4*)&sBl[r * 72 + c] = *(const uint4*)&g_w_l[off];
        }
        __syncthreads();

#pragma unroll
        for (int kk = 0; kk < 2; kk++) {
            uint32_t ah[4], al[4];
            uint32_t aoff = (uint32_t)(((wrow + (lane & 15)) * 40 + kk * 16 + ((lane >> 4) << 3)) * 2);
            ldsm4(ah, sAhb + aoff);
            ldsm4(al, sAlb + aoff);
#pragma unroll
            for (int nt = 0; nt < 8; nt++) {
                uint32_t bh[2], bl[2];
                uint32_t boff = (uint32_t)(((kk * 16 + (lane & 15)) * 72 + nt * 8) * 2);
                ldsm2t(bh, sBhb + boff);
                ldsm2t(bl, sBlb + boff);
                mma16816(acc[nt], ah, bh);
                mma16816(acc[nt], ah, bl);
                mma16816(acc[nt], al, bh);
            }
        }
    }

    int r0 = row0 + wrow + g;
    int r1 = r0 + 8;
    int p0 = (r0 & 255) * 16 + (r0 >> 8);
    int p1 = (r1 & 255) * 16 + (r1 >> 8);
#pragma unroll
    for (int nt = 0; nt < 8; nt++) {
        int col = ncol0 + nt * 8 + qc * 2;
        float b0 = bo[col], b1 = bo[col + 1];
        *(float2*)&out[(size_t)p0 * C_DIM + col] =
            make_float2(acc[nt][0] + b0, acc[nt][1] + b1);
        *(float2*)&out[(size_t)p1 * C_DIM + col] =
            make_float2(acc[nt][2] + b0, acc[nt][3] + b1);
    }
}

// ---------------- launch ----------------
extern "C" void kernel_launch(void* const* d_in, const int* in_sizes, int n_in,
                              void* d_out, int out_size) {
    const float* feat         = (const float*)d_in[0];
    const unsigned char* mask = (const unsigned char*)d_in[1];
    const float* Wq           = (const float*)d_in[2];
    const float* Wk           = (const float*)d_in[3];
    const float* Wv           = (const float*)d_in[4];
    const float* reg          = (const float*)d_in[5];
    const float* Wo           = (const float*)d_in[6];
    const float* bo           = (const float*)d_in[7];
    float* out                = (float*)d_out;

    (void)in_sizes; (void)n_in; (void)out_size;

    pack_mask_kernel<<<2048, 256>>>(mask);
    prep_kernel<<<dim3(10, 8, 17), dim3(32, 8)>>>(feat, reg, Wq, Wk, Wv, Wo);
    qkv_hmma_kernel<<<dim3(33, 15), 256>>>();

    cudaFuncSetAttribute(flash_kernel,
                         cudaFuncAttributeMaxDynamicSharedMemorySize, FLASH_SMEM);
    flash_kernel<<<dim3(32, N_HEADS), 128, FLASH_SMEM>>>();

    out_hmma_kernel<<<dim3(32, 5), 256>>>(bo, out);
}